// round 1
// baseline (speedup 1.0000x reference)
#include <cuda_runtime.h>
#include <math.h>

#define B_  8
#define T_  256
#define D_  1024
#define H_  512
#define S_  32896     /* T*(T+1)/2 */
#define K_  512
#define NG_ 10
#define NEGV (-1e20f)

/* ---------------- scratch (no allocations allowed) ---------------- */
__device__ float g_hs[B_ * T_ * H_];
__device__ float g_he[B_ * T_ * H_];
__device__ float g_scores[B_ * S_];
__device__ int   g_topidx[B_ * K_];

/* =======================================================================
 * Kernel 1: fused dual projection GEMM.
 * C[2048 x 1024] = X[2048 x 1024] @ [W_start | W_end] + [b_start | b_end]
 * 128x128 block tile, BK=16, 256 threads, 8x8 per thread, fp32.
 * ======================================================================= */
__global__ __launch_bounds__(256) void gemm_proj(
    const float* __restrict__ X,
    const float* __restrict__ Ws, const float* __restrict__ bs,
    const float* __restrict__ We, const float* __restrict__ be)
{
    __shared__ float sA[16][128];
    __shared__ float sB[16][128];

    const int t  = threadIdx.x;
    const int bx = blockIdx.x;      /* 0..7  -> N tile */
    const int by = blockIdx.y;      /* 0..15 -> M tile */
    const int ty = t >> 4;          /* 0..15 */
    const int tx = t & 15;          /* 0..15 */

    const bool useEnd = (bx >= 4);
    const float* W    = useEnd ? We : Ws;
    const int nOff    = (useEnd ? (bx - 4) : bx) * 128;   /* column in W (0..511 range base) */

    float acc[8][8];
#pragma unroll
    for (int i = 0; i < 8; i++)
#pragma unroll
        for (int j = 0; j < 8; j++) acc[i][j] = 0.f;

    const int arow = t >> 1;          /* 0..127 */
    const int acol = (t & 1) * 8;     /* 0 or 8 */
    const int brow = t >> 4;          /* 0..15  */
    const int bcol = (t & 15) * 8;    /* 0..120 */

    for (int k0 = 0; k0 < D_; k0 += 16) {
        const float* ap = X + (size_t)(by * 128 + arow) * D_ + k0 + acol;
        float4 a0 = *(const float4*)ap;
        float4 a1 = *(const float4*)(ap + 4);
        sA[acol + 0][arow] = a0.x; sA[acol + 1][arow] = a0.y;
        sA[acol + 2][arow] = a0.z; sA[acol + 3][arow] = a0.w;
        sA[acol + 4][arow] = a1.x; sA[acol + 5][arow] = a1.y;
        sA[acol + 6][arow] = a1.z; sA[acol + 7][arow] = a1.w;

        const float* bp = W + (size_t)(k0 + brow) * H_ + nOff + bcol;
        *(float4*)&sB[brow][bcol]     = *(const float4*)bp;
        *(float4*)&sB[brow][bcol + 4] = *(const float4*)(bp + 4);
        __syncthreads();

#pragma unroll
        for (int k = 0; k < 16; k++) {
            float a[8], b[8];
            float4 v;
            v = *(const float4*)&sA[k][ty * 8];     a[0]=v.x; a[1]=v.y; a[2]=v.z; a[3]=v.w;
            v = *(const float4*)&sA[k][ty * 8 + 4]; a[4]=v.x; a[5]=v.y; a[6]=v.z; a[7]=v.w;
            v = *(const float4*)&sB[k][tx * 8];     b[0]=v.x; b[1]=v.y; b[2]=v.z; b[3]=v.w;
            v = *(const float4*)&sB[k][tx * 8 + 4]; b[4]=v.x; b[5]=v.y; b[6]=v.z; b[7]=v.w;
#pragma unroll
            for (int i = 0; i < 8; i++)
#pragma unroll
                for (int j = 0; j < 8; j++)
                    acc[i][j] = fmaf(a[i], b[j], acc[i][j]);
        }
        __syncthreads();
    }

    const float* bias = useEnd ? be : bs;
    float* out        = useEnd ? g_he : g_hs;
#pragma unroll
    for (int i = 0; i < 8; i++) {
        int row = by * 128 + ty * 8 + i;
#pragma unroll
        for (int j = 0; j < 8; j += 4) {
            int n = nOff + tx * 8 + j;
            float4 v;
            v.x = acc[i][j]     + bias[n];
            v.y = acc[i][j + 1] + bias[n + 1];
            v.z = acc[i][j + 2] + bias[n + 2];
            v.w = acc[i][j + 3] + bias[n + 3];
            *(float4*)&out[(size_t)row * H_ + n] = v;
        }
    }
}

/* =======================================================================
 * Kernel 2: span scoring.
 * score(b,s,e) = sum_h relu(hs[b,s,h] + he[b,e,h]) * w[h] + b_score,
 * masked -> NEG. 64x64 (s x e) tile per block, 256 threads, 4x4/thread,
 * H chunked by 32 through smem. Only upper-triangular tiles launched.
 * ======================================================================= */
#define SCH 32
__global__ __launch_bounds__(256) void score_kernel(
    const float* __restrict__ wsc, const float* __restrict__ bsc,
    const int* __restrict__ msk)
{
    __shared__ float sA[SCH][64];     /* hs chunk, [h][s] */
    __shared__ float sB[SCH][64];     /* he chunk, [h][e] */
    __shared__ float sW[SCH];
    __shared__ int   sMs[64];
    __shared__ int   sMe[64];

    const int t = threadIdx.x;
    const int b = blockIdx.y;

    /* decode upper-triangular 4x4 tile pair from blockIdx.x (0..9) */
    int q = blockIdx.x, ti = 0;
    while (q >= (4 - ti)) { q -= (4 - ti); ti++; }
    const int tj = ti + q;
    const int s0 = ti * 64;
    const int e0 = tj * 64;

    if (t < 64)                 sMs[t]      = msk[b * T_ + s0 + t];
    else if (t < 128)           sMe[t - 64] = msk[b * T_ + e0 + (t - 64)];
    /* sync below covers this */

    const int sx = t & 15;     /* s group */
    const int ey = t >> 4;     /* e group */
    const int s_l = t >> 2;          /* 0..63 load row   */
    const int h_l = (t & 3) * 8;     /* 0..24 load h off */

    float acc[4][4];
#pragma unroll
    for (int i = 0; i < 4; i++)
#pragma unroll
        for (int j = 0; j < 4; j++) acc[i][j] = 0.f;

    for (int h0 = 0; h0 < H_; h0 += SCH) {
        __syncthreads();   /* protect previous iteration's reads */
        {
            const float* ap = g_hs + (size_t)(b * T_ + s0 + s_l) * H_ + h0 + h_l;
            float4 a0 = *(const float4*)ap;
            float4 a1 = *(const float4*)(ap + 4);
            sA[h_l + 0][s_l] = a0.x; sA[h_l + 1][s_l] = a0.y;
            sA[h_l + 2][s_l] = a0.z; sA[h_l + 3][s_l] = a0.w;
            sA[h_l + 4][s_l] = a1.x; sA[h_l + 5][s_l] = a1.y;
            sA[h_l + 6][s_l] = a1.z; sA[h_l + 7][s_l] = a1.w;

            const float* bp = g_he + (size_t)(b * T_ + e0 + s_l) * H_ + h0 + h_l;
            float4 b0 = *(const float4*)bp;
            float4 b1 = *(const float4*)(bp + 4);
            sB[h_l + 0][s_l] = b0.x; sB[h_l + 1][s_l] = b0.y;
            sB[h_l + 2][s_l] = b0.z; sB[h_l + 3][s_l] = b0.w;
            sB[h_l + 4][s_l] = b1.x; sB[h_l + 5][s_l] = b1.y;
            sB[h_l + 6][s_l] = b1.z; sB[h_l + 7][s_l] = b1.w;

            if (t < SCH) sW[t] = wsc[h0 + t];
        }
        __syncthreads();

#pragma unroll
        for (int h = 0; h < SCH; h++) {
            float4 av = *(const float4*)&sA[h][sx * 4];
            float4 bv = *(const float4*)&sB[h][ey * 4];
            float a[4] = {av.x, av.y, av.z, av.w};
            float bb[4] = {bv.x, bv.y, bv.z, bv.w};
            float wv = sW[h];
#pragma unroll
            for (int i = 0; i < 4; i++)
#pragma unroll
                for (int j = 0; j < 4; j++) {
                    float x = fmaxf(a[i] + bb[j], 0.f);
                    acc[i][j] = fmaf(x, wv, acc[i][j]);
                }
        }
    }

    const float bv = bsc[0];
#pragma unroll
    for (int i = 0; i < 4; i++) {
        int s = s0 + sx * 4 + i;
        int base = (s * (2 * T_ - s + 1)) >> 1;
        int ms = sMs[sx * 4 + i];
#pragma unroll
        for (int j = 0; j < 4; j++) {
            int e = e0 + ey * 4 + j;
            if (e >= s) {
                float v = (ms && sMe[ey * 4 + j]) ? (acc[i][j] + bv) : NEGV;
                g_scores[b * S_ + base + (e - s)] = v;
            }
        }
    }
}

/* =======================================================================
 * Kernel 3: exact top-K per batch via MSB-first radix select + ordered
 * compaction (ascending-index output, smallest-index tie-break == JAX).
 * One block of 1024 threads per batch.
 * ======================================================================= */
__device__ __forceinline__ unsigned fkey(float f)
{
    unsigned u = __float_as_uint(f);
    return u ^ ((u & 0x80000000u) ? 0xFFFFFFFFu : 0x80000000u);
}

__device__ int blockExclScan1024(int v, int* buf)
{
    const int t = threadIdx.x;
    buf[t] = v;
    __syncthreads();
#pragma unroll
    for (int off = 1; off < 1024; off <<= 1) {
        int x = (t >= off) ? buf[t - off] : 0;
        __syncthreads();
        buf[t] += x;
        __syncthreads();
    }
    int incl = buf[t];
    __syncthreads();
    return incl - v;
}

__global__ __launch_bounds__(1024) void topk_kernel()
{
    const int b = blockIdx.x;
    const int t = threadIdx.x;
    const float* sc = g_scores + (size_t)b * S_;

    __shared__ unsigned hist[256];
    __shared__ unsigned sh_prefix;
    __shared__ int      sh_rem;
    __shared__ int      scanbuf[1024];

    unsigned prefix = 0;
    int rem = K_;

    for (int pass = 0; pass < 4; pass++) {
        const int shift = 24 - pass * 8;
        if (t < 256) hist[t] = 0;
        __syncthreads();
        for (int i = t; i < S_; i += 1024) {
            unsigned u = fkey(sc[i]);
            bool match = (pass == 0) ||
                         ((u >> (shift + 8)) == (prefix >> (shift + 8)));
            if (match) atomicAdd(&hist[(u >> shift) & 255u], 1u);
        }
        __syncthreads();
        if (t == 0) {
            int r = rem;
            int d = 255;
            for (; d > 0; d--) {
                int c = (int)hist[d];
                if (r - c <= 0) break;
                r -= c;
            }
            sh_prefix = prefix | ((unsigned)d << shift);
            sh_rem = r;
        }
        __syncthreads();
        prefix = sh_prefix;
        rem    = sh_rem;
        __syncthreads();
    }

    const unsigned thr = prefix;  /* exact key of the K-th largest */
    const int need_eq  = rem;     /* # of ==thr to take (ascending index) */

    const int CHK = (S_ + 1023) / 1024;   /* 33 */
    const int lo = t * CHK;
    const int hi = (lo + CHK < S_) ? (lo + CHK) : S_;

    int ceq = 0, cgt = 0;
    for (int i = lo; i < hi; i++) {
        unsigned u = fkey(sc[i]);
        if (u > thr) cgt++;
        else if (u == thr) ceq++;
    }

    int eq_excl = blockExclScan1024(ceq, scanbuf);
    int take_eq = need_eq - eq_excl;
    if (take_eq < 0) take_eq = 0;
    if (take_eq > ceq) take_eq = ceq;
    int inc = cgt + take_eq;
    int out_excl = blockExclScan1024(inc, scanbuf);

    int pos = out_excl;
    int eqrank = eq_excl;
    for (int i = lo; i < hi; i++) {
        unsigned u = fkey(sc[i]);
        if (u > thr) {
            g_topidx[b * K_ + pos++] = i;
        } else if (u == thr) {
            if (eqrank < need_eq) g_topidx[b * K_ + pos++] = i;
            eqrank++;
        }
    }
}

/* =======================================================================
 * Kernel 4: gather + sigmoid + gold labels + BCE sum (deterministic,
 * single block).
 * ======================================================================= */
__global__ __launch_bounds__(1024) void finalize_kernel(
    const int* __restrict__ msk, const int* __restrict__ spans,
    float* __restrict__ out, int out_size)
{
    __shared__ int   gold[B_ * NG_];
    __shared__ float red[1024];
    const int t = threadIdx.x;

    if (t < B_ * NG_) {
        int s = spans[t * 2];
        int e = spans[t * 2 + 1];
        int gi = -1;
        if (s >= 0) gi = ((2 * s * T_ - s * s + s) >> 1) + (e - s);
        gold[t] = gi;
    }
    __syncthreads();

    float lsum = 0.f;
    for (int i = t; i < B_ * K_; i += 1024) {
        const int b = i / K_;
        const int idx = g_topidx[i];
        const float l = g_scores[(size_t)b * S_ + idx];

        /* decode (s, e) from triangular index */
        double disc = (double)(2 * T_ + 1) * (2 * T_ + 1) - 8.0 * (double)idx;
        int s = (int)(((2.0 * T_ + 1.0) - sqrt(disc)) * 0.5);
        if (s < 0) s = 0;
        if (s >= T_) s = T_ - 1;
        while (s > 0 && ((s * (2 * T_ - s + 1)) >> 1) > idx) s--;
        while (s + 1 < T_ && (((s + 1) * (2 * T_ - s)) >> 1) <= idx) s++;
        const int e = s + (idx - ((s * (2 * T_ - s + 1)) >> 1));

        const float mf = (msk[b * T_ + s] != 0 && msk[b * T_ + e] != 0) ? 1.f : 0.f;
        out[i] = mf / (1.f + expf(-l));

        float pred = 0.f;
#pragma unroll
        for (int g = 0; g < NG_; g++)
            if (gold[b * NG_ + g] == idx) pred = 1.f;

        const float bce = fmaxf(l, 0.f) - l * pred + log1pf(expf(-fabsf(l)));
        lsum += mf * bce;
    }

    /* zero any padding between probs and loss slot */
    for (int i = B_ * K_ + t; i < out_size - 1; i += 1024) out[i] = 0.f;

    red[t] = lsum;
    __syncthreads();
#pragma unroll
    for (int off = 512; off > 0; off >>= 1) {
        if (t < off) red[t] += red[t + off];
        __syncthreads();
    }
    if (t == 0) out[out_size - 1] = red[0];
}

/* ======================================================================= */
extern "C" void kernel_launch(void* const* d_in, const int* in_sizes, int n_in,
                              void* d_out, int out_size)
{
    const float* X   = (const float*)d_in[0];
    const int*   msk = (const int*)  d_in[1];
    const int*   asp = (const int*)  d_in[2];
    const float* Ws  = (const float*)d_in[3];
    const float* bs  = (const float*)d_in[4];
    const float* We  = (const float*)d_in[5];
    const float* be  = (const float*)d_in[6];
    const float* wsc = (const float*)d_in[7];
    const float* bsc = (const float*)d_in[8];
    float* out = (float*)d_out;

    gemm_proj<<<dim3(8, 16), 256>>>(X, Ws, bs, We, be);
    score_kernel<<<dim3(10, 8), 256>>>(wsc, bsc, msk);
    topk_kernel<<<8, 1024>>>();
    finalize_kernel<<<1, 1024>>>(msk, asp, out, out_size);
}

// round 3
// speedup vs baseline: 1.2205x; 1.2205x over previous
#include <cuda_runtime.h>
#include <stdint.h>
#include <math.h>

#define B_  8
#define T_  256
#define D_  1024
#define H_  512
#define S_  32896     /* T*(T+1)/2 */
#define K_  512
#define NG_ 10
#define NEGV (-1e20f)

#define M_  (B_ * T_)        /* 2048 */
#define N_  (2 * H_)         /* 1024: [start | end] */

/* ---------------- scratch (no allocations allowed) ---------------- */
__device__ float g_hs[B_ * T_ * H_];
__device__ float g_he[B_ * T_ * H_];
__device__ float g_scores[B_ * S_];
__device__ int   g_topidx[B_ * K_];
__device__ float g_loss[B_];

/* tf32 splits */
__device__ float g_Ahi[M_ * D_];
__device__ float g_Alo[M_ * D_];
__device__ float g_Bhi[N_ * D_];   /* W transposed: [n][k] */
__device__ float g_Blo[N_ * D_];

/* ======================= helpers ======================= */
__device__ __forceinline__ uint32_t f2tf32(float x)
{
    uint32_t r;
    asm("cvt.rna.tf32.f32 %0, %1;" : "=r"(r) : "f"(x));
    return r;
}

__device__ __forceinline__ void cpasync16(uint32_t smem_dst, const void* gsrc)
{
    asm volatile("cp.async.cg.shared.global [%0], [%1], 16;"
                 :: "r"(smem_dst), "l"(gsrc));
}

__device__ __forceinline__ void mma_tf32(float* c, const uint32_t a[4], const uint32_t b[2])
{
    asm volatile(
        "mma.sync.aligned.m16n8k8.row.col.f32.tf32.tf32.f32 "
        "{%0,%1,%2,%3}, {%4,%5,%6,%7}, {%8,%9}, {%0,%1,%2,%3};"
        : "+f"(c[0]), "+f"(c[1]), "+f"(c[2]), "+f"(c[3])
        : "r"(a[0]), "r"(a[1]), "r"(a[2]), "r"(a[3]), "r"(b[0]), "r"(b[1]));
}

/* =======================================================================
 * Prep A: split X into tf32 hi/lo (same [m][k] layout).
 * ======================================================================= */
__global__ __launch_bounds__(256) void prep_A(const float* __restrict__ X)
{
    int i = (blockIdx.x * 256 + threadIdx.x) * 4;
    if (i >= M_ * D_) return;
    float4 v = *(const float4*)(X + i);
    float4 hi, lo;
    hi.x = __uint_as_float(f2tf32(v.x)); lo.x = __uint_as_float(f2tf32(v.x - hi.x));
    hi.y = __uint_as_float(f2tf32(v.y)); lo.y = __uint_as_float(f2tf32(v.y - hi.y));
    hi.z = __uint_as_float(f2tf32(v.z)); lo.z = __uint_as_float(f2tf32(v.z - hi.z));
    hi.w = __uint_as_float(f2tf32(v.w)); lo.w = __uint_as_float(f2tf32(v.w - hi.w));
    *(float4*)(g_Ahi + i) = hi;
    *(float4*)(g_Alo + i) = lo;
}

/* =======================================================================
 * Prep B: transpose [k][n] -> [n][k] of the concatenated weight, with
 * tf32 split. 32x32 tiles via smem.
 * ======================================================================= */
__global__ __launch_bounds__(256) void prep_B(
    const float* __restrict__ Ws, const float* __restrict__ We)
{
    __shared__ float tile[32][33];
    const int tx = threadIdx.x & 31;
    const int ty = threadIdx.x >> 5;   /* 0..7 */
    const int n0 = blockIdx.x * 32;
    const int k0 = blockIdx.y * 32;

#pragma unroll
    for (int j = 0; j < 4; j++) {
        int k = k0 + ty + j * 8;
        int n = n0 + tx;
        float v = (n < H_) ? Ws[k * H_ + n] : We[k * H_ + (n - H_)];
        tile[ty + j * 8][tx] = v;    /* tile[k_local][n_local] */
    }
    __syncthreads();
#pragma unroll
    for (int j = 0; j < 4; j++) {
        int n = n0 + ty + j * 8;
        int k = k0 + tx;
        float v  = tile[tx][ty + j * 8];
        float hi = __uint_as_float(f2tf32(v));
        float lo = __uint_as_float(f2tf32(v - hi));
        g_Bhi[(size_t)n * D_ + k] = hi;
        g_Blo[(size_t)n * D_ + k] = lo;
    }
}

/* =======================================================================
 * Kernel 1: 3xTF32 tensor-core GEMM.
 * C[2048 x 1024] = X @ [W_start | W_end] + bias, fp32-accurate.
 * CTA tile 128x128, BK=16, 2-stage cp.async pipeline, 256 threads.
 * Warp layout 4(M) x 2(N): warp tile 32x64 -> 2 m16 x 8 n8 frags.
 * ======================================================================= */
#define BK    16
#define LDP   20                       /* padded row: 16 + 4 */
#define ARRF  (128 * LDP)              /* floats per tile array: 2560 */
#define STGF  (4 * ARRF)               /* floats per stage: 10240 */

__global__ __launch_bounds__(256) void gemm_mma(
    const float* __restrict__ bs, const float* __restrict__ be)
{
    extern __shared__ float smem[];

    const int t  = threadIdx.x;
    const int bx = blockIdx.x;          /* 0..7  N tile */
    const int by = blockIdx.y;          /* 0..15 M tile */
    const int m0 = by * 128;
    const int n0 = bx * 128;

    const int wid  = t >> 5;
    const int lane = t & 31;
    const int wm   = wid & 3;           /* M dir: 32 rows  */
    const int wn   = wid >> 2;          /* N dir: 64 cols  */
    const int gid  = lane >> 2;
    const int tig  = lane & 3;

    float acc[2][8][4];
#pragma unroll
    for (int mf = 0; mf < 2; mf++)
#pragma unroll
        for (int nf = 0; nf < 8; nf++)
#pragma unroll
            for (int r = 0; r < 4; r++) acc[mf][nf][r] = 0.f;

    /* global bases for the 4 streamed arrays */
    const float* gA[4];
    gA[0] = g_Ahi + (size_t)m0 * D_;
    gA[1] = g_Alo + (size_t)m0 * D_;
    gA[2] = g_Bhi + (size_t)n0 * D_;
    gA[3] = g_Blo + (size_t)n0 * D_;

    /* ---- issue loads for a chunk into stage s ---- */
    auto issue = [&](int kc, int s) {
        const int k0 = kc * BK;
        float* stg = smem + s * STGF;
#pragma unroll
        for (int arr = 0; arr < 4; arr++) {
#pragma unroll
            for (int i = 0; i < 2; i++) {
                int id  = t + 256 * i;          /* 0..511 */
                int row = id >> 2;              /* 0..127 */
                int c4  = (id & 3) * 4;         /* 0,4,8,12 */
                const float* src = gA[arr] + (size_t)row * D_ + k0 + c4;
                uint32_t dst = (uint32_t)__cvta_generic_to_shared(
                    stg + arr * ARRF + row * LDP + c4);
                cpasync16(dst, src);
            }
        }
        asm volatile("cp.async.commit_group;");
    };

    issue(0, 0);

    const int NCHUNK = D_ / BK;   /* 64 */
    for (int kc = 0; kc < NCHUNK; kc++) {
        const int cur = kc & 1;
        if (kc + 1 < NCHUNK) {
            issue(kc + 1, cur ^ 1);
            asm volatile("cp.async.wait_group 1;");
        } else {
            asm volatile("cp.async.wait_group 0;");
        }
        __syncthreads();

        const float* sAhi = smem + cur * STGF;
        const float* sAlo = sAhi + ARRF;
        const float* sBhi = sAlo + ARRF;
        const float* sBlo = sBhi + ARRF;

#pragma unroll
        for (int ks = 0; ks < 2; ks++) {
            const int kb = ks * 8;
            uint32_t ah[2][4], al[2][4];
#pragma unroll
            for (int mf = 0; mf < 2; mf++) {
                int r = wm * 32 + mf * 16 + gid;
                int c = kb + tig;
                ah[mf][0] = __float_as_uint(sAhi[r * LDP + c]);
                ah[mf][1] = __float_as_uint(sAhi[(r + 8) * LDP + c]);
                ah[mf][2] = __float_as_uint(sAhi[r * LDP + c + 4]);
                ah[mf][3] = __float_as_uint(sAhi[(r + 8) * LDP + c + 4]);
                al[mf][0] = __float_as_uint(sAlo[r * LDP + c]);
                al[mf][1] = __float_as_uint(sAlo[(r + 8) * LDP + c]);
                al[mf][2] = __float_as_uint(sAlo[r * LDP + c + 4]);
                al[mf][3] = __float_as_uint(sAlo[(r + 8) * LDP + c + 4]);
            }
            uint32_t bh[8][2], bl[8][2];
#pragma unroll
            for (int nf = 0; nf < 8; nf++) {
                int r = wn * 64 + nf * 8 + gid;
                int c = kb + tig;
                bh[nf][0] = __float_as_uint(sBhi[r * LDP + c]);
                bh[nf][1] = __float_as_uint(sBhi[r * LDP + c + 4]);
                bl[nf][0] = __float_as_uint(sBlo[r * LDP + c]);
                bl[nf][1] = __float_as_uint(sBlo[r * LDP + c + 4]);
            }
#pragma unroll
            for (int mf = 0; mf < 2; mf++)
#pragma unroll
                for (int nf = 0; nf < 8; nf++) {
                    mma_tf32(acc[mf][nf], ah[mf], bh[nf]);
                    mma_tf32(acc[mf][nf], ah[mf], bl[nf]);
                    mma_tf32(acc[mf][nf], al[mf], bh[nf]);
                }
        }
        __syncthreads();
    }

    /* ---- epilogue: bias + store to g_hs / g_he ---- */
    const bool  isStart = (bx < 4);
    float*      out     = isStart ? g_hs : g_he;
    const float* bias   = isStart ? bs : be;
    const int   nbase   = n0 - (isStart ? 0 : H_);

#pragma unroll
    for (int mf = 0; mf < 2; mf++) {
        int row = m0 + wm * 32 + mf * 16 + gid;
#pragma unroll
        for (int nf = 0; nf < 8; nf++) {
            int nl = nbase + wn * 64 + nf * 8 + tig * 2;
            float b0 = bias[nl], b1 = bias[nl + 1];
            float2 v0 = make_float2(acc[mf][nf][0] + b0, acc[mf][nf][1] + b1);
            float2 v1 = make_float2(acc[mf][nf][2] + b0, acc[mf][nf][3] + b1);
            *(float2*)&out[(size_t)row * H_ + nl]       = v0;
            *(float2*)&out[(size_t)(row + 8) * H_ + nl] = v1;
        }
    }
}

/* =======================================================================
 * Kernel 2: span scoring.
 * ======================================================================= */
#define SCH 32
__global__ __launch_bounds__(256) void score_kernel(
    const float* __restrict__ wsc, const float* __restrict__ bsc,
    const int* __restrict__ msk)
{
    __shared__ float sA[SCH][64];
    __shared__ float sB[SCH][64];
    __shared__ float sW[SCH];
    __shared__ int   sMs[64];
    __shared__ int   sMe[64];

    const int t = threadIdx.x;
    const int b = blockIdx.y;

    int q = blockIdx.x, ti = 0;
    while (q >= (4 - ti)) { q -= (4 - ti); ti++; }
    const int tj = ti + q;
    const int s0 = ti * 64;
    const int e0 = tj * 64;

    if (t < 64)       sMs[t]      = msk[b * T_ + s0 + t];
    else if (t < 128) sMe[t - 64] = msk[b * T_ + e0 + (t - 64)];

    const int sx = t & 15;
    const int ey = t >> 4;
    const int s_l = t >> 2;
    const int h_l = (t & 3) * 8;

    float acc[4][4];
#pragma unroll
    for (int i = 0; i < 4; i++)
#pragma unroll
        for (int j = 0; j < 4; j++) acc[i][j] = 0.f;

    for (int h0 = 0; h0 < H_; h0 += SCH) {
        __syncthreads();
        {
            const float* ap = g_hs + (size_t)(b * T_ + s0 + s_l) * H_ + h0 + h_l;
            float4 a0 = *(const float4*)ap;
            float4 a1 = *(const float4*)(ap + 4);
            sA[h_l + 0][s_l] = a0.x; sA[h_l + 1][s_l] = a0.y;
            sA[h_l + 2][s_l] = a0.z; sA[h_l + 3][s_l] = a0.w;
            sA[h_l + 4][s_l] = a1.x; sA[h_l + 5][s_l] = a1.y;
            sA[h_l + 6][s_l] = a1.z; sA[h_l + 7][s_l] = a1.w;

            const float* bp = g_he + (size_t)(b * T_ + e0 + s_l) * H_ + h0 + h_l;
            float4 b0 = *(const float4*)bp;
            float4 b1 = *(const float4*)(bp + 4);
            sB[h_l + 0][s_l] = b0.x; sB[h_l + 1][s_l] = b0.y;
            sB[h_l + 2][s_l] = b0.z; sB[h_l + 3][s_l] = b0.w;
            sB[h_l + 4][s_l] = b1.x; sB[h_l + 5][s_l] = b1.y;
            sB[h_l + 6][s_l] = b1.z; sB[h_l + 7][s_l] = b1.w;

            if (t < SCH) sW[t] = wsc[h0 + t];
        }
        __syncthreads();

#pragma unroll
        for (int h = 0; h < SCH; h++) {
            float4 av = *(const float4*)&sA[h][sx * 4];
            float4 bv = *(const float4*)&sB[h][ey * 4];
            float a[4] = {av.x, av.y, av.z, av.w};
            float bb[4] = {bv.x, bv.y, bv.z, bv.w};
            float wv = sW[h];
#pragma unroll
            for (int i = 0; i < 4; i++)
#pragma unroll
                for (int j = 0; j < 4; j++) {
                    float x = fmaxf(a[i] + bb[j], 0.f);
                    acc[i][j] = fmaf(x, wv, acc[i][j]);
                }
        }
    }

    const float bv = bsc[0];
#pragma unroll
    for (int i = 0; i < 4; i++) {
        int s = s0 + sx * 4 + i;
        int base = (s * (2 * T_ - s + 1)) >> 1;
        int ms = sMs[sx * 4 + i];
#pragma unroll
        for (int j = 0; j < 4; j++) {
            int e = e0 + ey * 4 + j;
            if (e >= s) {
                float v = (ms && sMe[ey * 4 + j]) ? (acc[i][j] + bv) : NEGV;
                g_scores[b * S_ + base + (e - s)] = v;
            }
        }
    }
}

/* =======================================================================
 * Kernel 3: exact top-K per batch via MSB-first radix select + ordered
 * compaction.
 * ======================================================================= */
__device__ __forceinline__ unsigned fkey(float f)
{
    unsigned u = __float_as_uint(f);
    return u ^ ((u & 0x80000000u) ? 0xFFFFFFFFu : 0x80000000u);
}

__device__ int blockExclScan1024(int v, int* buf)
{
    const int t = threadIdx.x;
    buf[t] = v;
    __syncthreads();
#pragma unroll
    for (int off = 1; off < 1024; off <<= 1) {
        int x = (t >= off) ? buf[t - off] : 0;
        __syncthreads();
        buf[t] += x;
        __syncthreads();
    }
    int incl = buf[t];
    __syncthreads();
    return incl - v;
}

__global__ __launch_bounds__(1024) void topk_kernel()
{
    const int b = blockIdx.x;
    const int t = threadIdx.x;
    const float* sc = g_scores + (size_t)b * S_;

    __shared__ unsigned hist[256];
    __shared__ unsigned sh_prefix;
    __shared__ int      sh_rem;
    __shared__ int      scanbuf[1024];

    unsigned prefix = 0;
    int rem = K_;

    for (int pass = 0; pass < 4; pass++) {
        const int shift = 24 - pass * 8;
        if (t < 256) hist[t] = 0;
        __syncthreads();
        for (int i = t; i < S_; i += 1024) {
            unsigned u = fkey(sc[i]);
            bool match = (pass == 0) ||
                         ((u >> (shift + 8)) == (prefix >> (shift + 8)));
            if (match) atomicAdd(&hist[(u >> shift) & 255u], 1u);
        }
        __syncthreads();
        if (t == 0) {
            int r = rem;
            int d = 255;
            for (; d > 0; d--) {
                int c = (int)hist[d];
                if (r - c <= 0) break;
                r -= c;
            }
            sh_prefix = prefix | ((unsigned)d << shift);
            sh_rem = r;
        }
        __syncthreads();
        prefix = sh_prefix;
        rem    = sh_rem;
        __syncthreads();
    }

    const unsigned thr = prefix;
    const int need_eq  = rem;

    const int CHK = (S_ + 1023) / 1024;
    const int lo = t * CHK;
    const int hi = (lo + CHK < S_) ? (lo + CHK) : S_;

    int ceq = 0, cgt = 0;
    for (int i = lo; i < hi; i++) {
        unsigned u = fkey(sc[i]);
        if (u > thr) cgt++;
        else if (u == thr) ceq++;
    }

    int eq_excl = blockExclScan1024(ceq, scanbuf);
    int take_eq = need_eq - eq_excl;
    if (take_eq < 0) take_eq = 0;
    if (take_eq > ceq) take_eq = ceq;
    int inc = cgt + take_eq;
    int out_excl = blockExclScan1024(inc, scanbuf);

    int pos = out_excl;
    int eqrank = eq_excl;
    for (int i = lo; i < hi; i++) {
        unsigned u = fkey(sc[i]);
        if (u > thr) {
            g_topidx[b * K_ + pos++] = i;
        } else if (u == thr) {
            if (eqrank < need_eq) g_topidx[b * K_ + pos++] = i;
            eqrank++;
        }
    }
}

/* =======================================================================
 * Kernel 4a: per-batch gather + sigmoid + BCE partial sums (8 blocks).
 * ======================================================================= */
__global__ __launch_bounds__(512) void finalize_kernel(
    const int* __restrict__ msk, const int* __restrict__ spans,
    float* __restrict__ out)
{
    __shared__ int   gold[NG_];
    __shared__ float red[512];
    const int b = blockIdx.x;
    const int t = threadIdx.x;

    if (t < NG_) {
        int s = spans[(b * NG_ + t) * 2];
        int e = spans[(b * NG_ + t) * 2 + 1];
        int gi = -1;
        if (s >= 0) gi = ((2 * s * T_ - s * s + s) >> 1) + (e - s);
        gold[t] = gi;
    }
    __syncthreads();

    const int idx = g_topidx[b * K_ + t];
    const float l = g_scores[(size_t)b * S_ + idx];

    /* decode (s, e) from triangular index */
    double disc = (double)(2 * T_ + 1) * (2 * T_ + 1) - 8.0 * (double)idx;
    int s = (int)(((2.0 * T_ + 1.0) - sqrt(disc)) * 0.5);
    if (s < 0) s = 0;
    if (s >= T_) s = T_ - 1;
    while (s > 0 && ((s * (2 * T_ - s + 1)) >> 1) > idx) s--;
    while (s + 1 < T_ && (((s + 1) * (2 * T_ - s)) >> 1) <= idx) s++;
    const int e = s + (idx - ((s * (2 * T_ - s + 1)) >> 1));

    const float mf = (msk[b * T_ + s] != 0 && msk[b * T_ + e] != 0) ? 1.f : 0.f;
    out[b * K_ + t] = mf / (1.f + expf(-l));

    float pred = 0.f;
#pragma unroll
    for (int g = 0; g < NG_; g++)
        if (gold[g] == idx) pred = 1.f;

    const float bce = fmaxf(l, 0.f) - l * pred + log1pf(expf(-fabsf(l)));
    red[t] = mf * bce;
    __syncthreads();
#pragma unroll
    for (int off = 256; off > 0; off >>= 1) {
        if (t < off) red[t] += red[t + off];
        __syncthreads();
    }
    if (t == 0) g_loss[b] = red[0];
}

/* Kernel 4b: deterministic loss sum + pad zeroing. */
__global__ __launch_bounds__(256) void loss_sum_kernel(float* __restrict__ out, int out_size)
{
    const int t = threadIdx.x;
    for (int i = B_ * K_ + t; i < out_size - 1; i += 256) out[i] = 0.f;
    if (t == 0) {
        float s = 0.f;
#pragma unroll
        for (int b = 0; b < B_; b++) s += g_loss[b];
        out[out_size - 1] = s;
    }
}

/* ======================================================================= */
extern "C" void kernel_launch(void* const* d_in, const int* in_sizes, int n_in,
                              void* d_out, int out_size)
{
    const float* X   = (const float*)d_in[0];
    const int*   msk = (const int*)  d_in[1];
    const int*   asp = (const int*)  d_in[2];
    const float* Ws  = (const float*)d_in[3];
    const float* bs  = (const float*)d_in[4];
    const float* We  = (const float*)d_in[5];
    const float* be  = (const float*)d_in[6];
    const float* wsc = (const float*)d_in[7];
    const float* bsc = (const float*)d_in[8];
    float* out = (float*)d_out;

    static int smem_set = 0;
    if (!smem_set) {
        cudaFuncSetAttribute(gemm_mma,
                             cudaFuncAttributeMaxDynamicSharedMemorySize,
                             2 * STGF * (int)sizeof(float));
        smem_set = 1;
    }

    prep_A<<<(M_ * D_ / 4 + 255) / 256, 256>>>(X);
    prep_B<<<dim3(N_ / 32, D_ / 32), 256>>>(Ws, We);
    gemm_mma<<<dim3(8, 16), 256, 2 * STGF * sizeof(float)>>>(bs, be);
    score_kernel<<<dim3(10, 8), 256>>>(wsc, bsc, msk);
    topk_kernel<<<8, 1024>>>();
    finalize_kernel<<<8, 512>>>(msk, asp, out);
    loss_sum_kernel<<<1, 256>>>(out, out_size);
}

// round 4
// speedup vs baseline: 1.2854x; 1.0532x over previous
#include <cuda_runtime.h>
#include <stdint.h>
#include <math.h>

#define B_  8
#define T_  256
#define D_  1024
#define H_  512
#define S_  32896     /* T*(T+1)/2 */
#define K_  512
#define NG_ 10
#define NEGV (-1e20f)

#define M_  (B_ * T_)        /* 2048 */
#define N_  (2 * H_)         /* 1024: [start | end] */

/* ---------------- scratch (no allocations allowed) ---------------- */
__device__ float g_hs[B_ * T_ * H_];
__device__ float g_he[B_ * T_ * H_];
__device__ float g_scores[B_ * S_];
__device__ int   g_topidx[B_ * K_];
__device__ float g_loss[B_];

/* tf32 splits */
__device__ float g_Ahi[M_ * D_];
__device__ float g_Alo[M_ * D_];
__device__ float g_Bhi[N_ * D_];   /* W transposed: [n][k] */
__device__ float g_Blo[N_ * D_];

/* ======================= helpers ======================= */
__device__ __forceinline__ uint32_t f2tf32(float x)
{
    uint32_t r;
    asm("cvt.rna.tf32.f32 %0, %1;" : "=r"(r) : "f"(x));
    return r;
}

__device__ __forceinline__ void cpasync16(uint32_t smem_dst, const void* gsrc)
{
    asm volatile("cp.async.cg.shared.global [%0], [%1], 16;"
                 :: "r"(smem_dst), "l"(gsrc));
}

__device__ __forceinline__ void mma_tf32(float* c, const uint32_t a[4], const uint32_t b[2])
{
    asm volatile(
        "mma.sync.aligned.m16n8k8.row.col.f32.tf32.tf32.f32 "
        "{%0,%1,%2,%3}, {%4,%5,%6,%7}, {%8,%9}, {%0,%1,%2,%3};"
        : "+f"(c[0]), "+f"(c[1]), "+f"(c[2]), "+f"(c[3])
        : "r"(a[0]), "r"(a[1]), "r"(a[2]), "r"(a[3]), "r"(b[0]), "r"(b[1]));
}

/* =======================================================================
 * Prep A: split X into tf32 hi/lo (same [m][k] layout).
 * ======================================================================= */
__global__ __launch_bounds__(256) void prep_A(const float* __restrict__ X)
{
    int i = (blockIdx.x * 256 + threadIdx.x) * 4;
    if (i >= M_ * D_) return;
    float4 v = *(const float4*)(X + i);
    float4 hi, lo;
    hi.x = __uint_as_float(f2tf32(v.x)); lo.x = __uint_as_float(f2tf32(v.x - hi.x));
    hi.y = __uint_as_float(f2tf32(v.y)); lo.y = __uint_as_float(f2tf32(v.y - hi.y));
    hi.z = __uint_as_float(f2tf32(v.z)); lo.z = __uint_as_float(f2tf32(v.z - hi.z));
    hi.w = __uint_as_float(f2tf32(v.w)); lo.w = __uint_as_float(f2tf32(v.w - hi.w));
    *(float4*)(g_Ahi + i) = hi;
    *(float4*)(g_Alo + i) = lo;
}

/* =======================================================================
 * Prep B: transpose [k][n] -> [n][k] of the concatenated weight, with
 * tf32 split. 32x32 tiles via smem.
 * ======================================================================= */
__global__ __launch_bounds__(256) void prep_B(
    const float* __restrict__ Ws, const float* __restrict__ We)
{
    __shared__ float tile[32][33];
    const int tx = threadIdx.x & 31;
    const int ty = threadIdx.x >> 5;   /* 0..7 */
    const int n0 = blockIdx.x * 32;
    const int k0 = blockIdx.y * 32;

#pragma unroll
    for (int j = 0; j < 4; j++) {
        int k = k0 + ty + j * 8;
        int n = n0 + tx;
        float v = (n < H_) ? Ws[k * H_ + n] : We[k * H_ + (n - H_)];
        tile[ty + j * 8][tx] = v;
    }
    __syncthreads();
#pragma unroll
    for (int j = 0; j < 4; j++) {
        int n = n0 + ty + j * 8;
        int k = k0 + tx;
        float v  = tile[tx][ty + j * 8];
        float hi = __uint_as_float(f2tf32(v));
        float lo = __uint_as_float(f2tf32(v - hi));
        g_Bhi[(size_t)n * D_ + k] = hi;
        g_Blo[(size_t)n * D_ + k] = lo;
    }
}

/* =======================================================================
 * Kernel 1: 3xTF32 tensor-core GEMM (unchanged from round 3).
 * ======================================================================= */
#define BK    16
#define LDP   20
#define ARRF  (128 * LDP)
#define STGF  (4 * ARRF)

__global__ __launch_bounds__(256) void gemm_mma(
    const float* __restrict__ bs, const float* __restrict__ be)
{
    extern __shared__ float smem[];

    const int t  = threadIdx.x;
    const int bx = blockIdx.x;
    const int by = blockIdx.y;
    const int m0 = by * 128;
    const int n0 = bx * 128;

    const int wid  = t >> 5;
    const int lane = t & 31;
    const int wm   = wid & 3;
    const int wn   = wid >> 2;
    const int gid  = lane >> 2;
    const int tig  = lane & 3;

    float acc[2][8][4];
#pragma unroll
    for (int mf = 0; mf < 2; mf++)
#pragma unroll
        for (int nf = 0; nf < 8; nf++)
#pragma unroll
            for (int r = 0; r < 4; r++) acc[mf][nf][r] = 0.f;

    const float* gA[4];
    gA[0] = g_Ahi + (size_t)m0 * D_;
    gA[1] = g_Alo + (size_t)m0 * D_;
    gA[2] = g_Bhi + (size_t)n0 * D_;
    gA[3] = g_Blo + (size_t)n0 * D_;

    auto issue = [&](int kc, int s) {
        const int k0 = kc * BK;
        float* stg = smem + s * STGF;
#pragma unroll
        for (int arr = 0; arr < 4; arr++) {
#pragma unroll
            for (int i = 0; i < 2; i++) {
                int id  = t + 256 * i;
                int row = id >> 2;
                int c4  = (id & 3) * 4;
                const float* src = gA[arr] + (size_t)row * D_ + k0 + c4;
                uint32_t dst = (uint32_t)__cvta_generic_to_shared(
                    stg + arr * ARRF + row * LDP + c4);
                cpasync16(dst, src);
            }
        }
        asm volatile("cp.async.commit_group;");
    };

    issue(0, 0);

    const int NCHUNK = D_ / BK;
    for (int kc = 0; kc < NCHUNK; kc++) {
        const int cur = kc & 1;
        if (kc + 1 < NCHUNK) {
            issue(kc + 1, cur ^ 1);
            asm volatile("cp.async.wait_group 1;");
        } else {
            asm volatile("cp.async.wait_group 0;");
        }
        __syncthreads();

        const float* sAhi = smem + cur * STGF;
        const float* sAlo = sAhi + ARRF;
        const float* sBhi = sAlo + ARRF;
        const float* sBlo = sBhi + ARRF;

#pragma unroll
        for (int ks = 0; ks < 2; ks++) {
            const int kb = ks * 8;
            uint32_t ah[2][4], al[2][4];
#pragma unroll
            for (int mf = 0; mf < 2; mf++) {
                int r = wm * 32 + mf * 16 + gid;
                int c = kb + tig;
                ah[mf][0] = __float_as_uint(sAhi[r * LDP + c]);
                ah[mf][1] = __float_as_uint(sAhi[(r + 8) * LDP + c]);
                ah[mf][2] = __float_as_uint(sAhi[r * LDP + c + 4]);
                ah[mf][3] = __float_as_uint(sAhi[(r + 8) * LDP + c + 4]);
                al[mf][0] = __float_as_uint(sAlo[r * LDP + c]);
                al[mf][1] = __float_as_uint(sAlo[(r + 8) * LDP + c]);
                al[mf][2] = __float_as_uint(sAlo[r * LDP + c + 4]);
                al[mf][3] = __float_as_uint(sAlo[(r + 8) * LDP + c + 4]);
            }
            uint32_t bh[8][2], bl[8][2];
#pragma unroll
            for (int nf = 0; nf < 8; nf++) {
                int r = wn * 64 + nf * 8 + gid;
                int c = kb + tig;
                bh[nf][0] = __float_as_uint(sBhi[r * LDP + c]);
                bh[nf][1] = __float_as_uint(sBhi[r * LDP + c + 4]);
                bl[nf][0] = __float_as_uint(sBlo[r * LDP + c]);
                bl[nf][1] = __float_as_uint(sBlo[r * LDP + c + 4]);
            }
#pragma unroll
            for (int mf = 0; mf < 2; mf++)
#pragma unroll
                for (int nf = 0; nf < 8; nf++) {
                    mma_tf32(acc[mf][nf], ah[mf], bh[nf]);
                    mma_tf32(acc[mf][nf], ah[mf], bl[nf]);
                    mma_tf32(acc[mf][nf], al[mf], bh[nf]);
                }
        }
        __syncthreads();
    }

    const bool  isStart = (bx < 4);
    float*      out     = isStart ? g_hs : g_he;
    const float* bias   = isStart ? bs : be;
    const int   nbase   = n0 - (isStart ? 0 : H_);

#pragma unroll
    for (int mf = 0; mf < 2; mf++) {
        int row = m0 + wm * 32 + mf * 16 + gid;
#pragma unroll
        for (int nf = 0; nf < 8; nf++) {
            int nl = nbase + wn * 64 + nf * 8 + tig * 2;
            float b0 = bias[nl], b1 = bias[nl + 1];
            float2 v0 = make_float2(acc[mf][nf][0] + b0, acc[mf][nf][1] + b1);
            float2 v1 = make_float2(acc[mf][nf][2] + b0, acc[mf][nf][3] + b1);
            *(float2*)&out[(size_t)row * H_ + nl]       = v0;
            *(float2*)&out[(size_t)(row + 8) * H_ + nl] = v1;
        }
    }
}

/* =======================================================================
 * Kernel 2: span scoring v2 — 32x32 (s,e) tiles, 288 blocks total.
 * 256 threads, 2x2 outputs/thread. Same sequential h-sum order as before.
 * ======================================================================= */
#define SCH 32
__global__ __launch_bounds__(256) void score_kernel(
    const float* __restrict__ wsc, const float* __restrict__ bsc,
    const int* __restrict__ msk)
{
    __shared__ float sA[SCH][34];     /* hs chunk, [h][s], pad 34 (8B align) */
    __shared__ float sB[SCH][34];     /* he chunk, [h][e] */
    __shared__ float sW[SCH];
    __shared__ int   sMs[32];
    __shared__ int   sMe[32];

    const int t = threadIdx.x;
    const int b = blockIdx.y;

    /* decode upper-triangular tile pair (8x8 groups of 32) */
    int q = blockIdx.x, ti = 0;
    while (q >= (8 - ti)) { q -= (8 - ti); ti++; }
    const int tj = ti + q;
    const int s0 = ti * 32;
    const int e0 = tj * 32;

    if (t < 32)      sMs[t]      = msk[b * T_ + s0 + t];
    else if (t < 64) sMe[t - 32] = msk[b * T_ + e0 + (t - 32)];

    const int sx = t & 15;           /* s group: 2 rows  */
    const int ey = t >> 4;           /* e group: 2 cols  */
    const int s_l = t >> 3;          /* load row 0..31   */
    const int h_l = (t & 7) * 4;     /* load h   0..28   */

    float acc00 = 0.f, acc01 = 0.f, acc10 = 0.f, acc11 = 0.f;

    for (int h0 = 0; h0 < H_; h0 += SCH) {
        __syncthreads();
        {
            float4 a = *(const float4*)(g_hs + (size_t)(b * T_ + s0 + s_l) * H_ + h0 + h_l);
            sA[h_l + 0][s_l] = a.x; sA[h_l + 1][s_l] = a.y;
            sA[h_l + 2][s_l] = a.z; sA[h_l + 3][s_l] = a.w;
            float4 e = *(const float4*)(g_he + (size_t)(b * T_ + e0 + s_l) * H_ + h0 + h_l);
            sB[h_l + 0][s_l] = e.x; sB[h_l + 1][s_l] = e.y;
            sB[h_l + 2][s_l] = e.z; sB[h_l + 3][s_l] = e.w;
            if (t < SCH) sW[t] = wsc[h0 + t];
        }
        __syncthreads();

#pragma unroll
        for (int h = 0; h < SCH; h++) {
            float2 av = *(const float2*)&sA[h][sx * 2];
            float2 bv = *(const float2*)&sB[h][ey * 2];
            float wv = sW[h];
            acc00 = fmaf(fmaxf(av.x + bv.x, 0.f), wv, acc00);
            acc01 = fmaf(fmaxf(av.x + bv.y, 0.f), wv, acc01);
            acc10 = fmaf(fmaxf(av.y + bv.x, 0.f), wv, acc10);
            acc11 = fmaf(fmaxf(av.y + bv.y, 0.f), wv, acc11);
        }
    }

    const float bval = bsc[0];
    float accs[2][2] = {{acc00, acc01}, {acc10, acc11}};
#pragma unroll
    for (int i = 0; i < 2; i++) {
        int s = s0 + sx * 2 + i;
        int base = (s * (2 * T_ - s + 1)) >> 1;
        int ms = sMs[sx * 2 + i];
#pragma unroll
        for (int j = 0; j < 2; j++) {
            int e = e0 + ey * 2 + j;
            if (e >= s) {
                float v = (ms && sMe[ey * 2 + j]) ? (accs[i][j] + bval) : NEGV;
                g_scores[b * S_ + base + (e - s)] = v;
            }
        }
    }
}

/* =======================================================================
 * Kernel 3: exact top-K — warp-aggregated histogram + shuffle scan.
 * ======================================================================= */
__device__ __forceinline__ unsigned fkey(float f)
{
    unsigned u = __float_as_uint(f);
    return u ^ ((u & 0x80000000u) ? 0xFFFFFFFFu : 0x80000000u);
}

__device__ int blockExclScan1024(int v)
{
    __shared__ int ws[32];
    const int lane = threadIdx.x & 31;
    const int wid  = threadIdx.x >> 5;

    int incl = v;
#pragma unroll
    for (int o = 1; o < 32; o <<= 1) {
        int x = __shfl_up_sync(0xFFFFFFFFu, incl, o);
        if (lane >= o) incl += x;
    }
    if (lane == 31) ws[wid] = incl;
    __syncthreads();
    if (wid == 0) {
        int s = ws[lane];
#pragma unroll
        for (int o = 1; o < 32; o <<= 1) {
            int x = __shfl_up_sync(0xFFFFFFFFu, s, o);
            if (lane >= o) s += x;
        }
        ws[lane] = s;
    }
    __syncthreads();
    int base = (wid > 0) ? ws[wid - 1] : 0;
    int r = base + incl - v;
    __syncthreads();      /* ws reusable after return */
    return r;
}

__global__ __launch_bounds__(1024) void topk_kernel()
{
    const int b = blockIdx.x;
    const int t = threadIdx.x;
    const int lane = t & 31;
    const float* sc = g_scores + (size_t)b * S_;

    __shared__ unsigned hist[256];
    __shared__ unsigned sh_prefix;
    __shared__ int      sh_rem;

    unsigned prefix = 0;
    int rem = K_;

    for (int pass = 0; pass < 4; pass++) {
        const int shift = 24 - pass * 8;
        if (t < 256) hist[t] = 0;
        __syncthreads();
        /* S_ = 32*1024 + 128: all loop trips have whole warps active */
        for (int i = t; i < S_; i += 1024) {
            unsigned u = fkey(sc[i]);
            bool match = (pass == 0) ||
                         ((u >> (shift + 8)) == (prefix >> (shift + 8)));
            unsigned am = __ballot_sync(0xFFFFFFFFu, match);
            if (match) {
                unsigned d = (u >> shift) & 255u;
                unsigned peers = __match_any_sync(am, d);
                if ((__ffs(peers) - 1) == lane)
                    atomicAdd(&hist[d], __popc(peers));
            }
        }
        __syncthreads();
        if (t == 0) {
            int r = rem;
            int d = 255;
            for (; d > 0; d--) {
                int c = (int)hist[d];
                if (r - c <= 0) break;
                r -= c;
            }
            sh_prefix = prefix | ((unsigned)d << shift);
            sh_rem = r;
        }
        __syncthreads();
        prefix = sh_prefix;
        rem    = sh_rem;
        __syncthreads();
    }

    const unsigned thr = prefix;
    const int need_eq  = rem;

    const int CHK = (S_ + 1023) / 1024;   /* 33 */
    const int lo = t * CHK;
    const int hi = (lo + CHK < S_) ? (lo + CHK) : S_;

    int ceq = 0, cgt = 0;
    for (int i = lo; i < hi; i++) {
        unsigned u = fkey(sc[i]);
        if (u > thr) cgt++;
        else if (u == thr) ceq++;
    }

    int eq_excl = blockExclScan1024(ceq);
    int take_eq = need_eq - eq_excl;
    if (take_eq < 0) take_eq = 0;
    if (take_eq > ceq) take_eq = ceq;
    int inc = cgt + take_eq;
    int out_excl = blockExclScan1024(inc);

    int pos = out_excl;
    int eqrank = eq_excl;
    for (int i = lo; i < hi; i++) {
        unsigned u = fkey(sc[i]);
        if (u > thr) {
            g_topidx[b * K_ + pos++] = i;
        } else if (u == thr) {
            if (eqrank < need_eq) g_topidx[b * K_ + pos++] = i;
            eqrank++;
        }
    }
}

/* =======================================================================
 * Kernel 4a: per-batch gather + sigmoid + BCE partial sums (8 blocks).
 * ======================================================================= */
__global__ __launch_bounds__(512) void finalize_kernel(
    const int* __restrict__ msk, const int* __restrict__ spans,
    float* __restrict__ out)
{
    __shared__ int   gold[NG_];
    __shared__ float red[512];
    const int b = blockIdx.x;
    const int t = threadIdx.x;

    if (t < NG_) {
        int s = spans[(b * NG_ + t) * 2];
        int e = spans[(b * NG_ + t) * 2 + 1];
        int gi = -1;
        if (s >= 0) gi = ((2 * s * T_ - s * s + s) >> 1) + (e - s);
        gold[t] = gi;
    }
    __syncthreads();

    const int idx = g_topidx[b * K_ + t];
    const float l = g_scores[(size_t)b * S_ + idx];

    double disc = (double)(2 * T_ + 1) * (2 * T_ + 1) - 8.0 * (double)idx;
    int s = (int)(((2.0 * T_ + 1.0) - sqrt(disc)) * 0.5);
    if (s < 0) s = 0;
    if (s >= T_) s = T_ - 1;
    while (s > 0 && ((s * (2 * T_ - s + 1)) >> 1) > idx) s--;
    while (s + 1 < T_ && (((s + 1) * (2 * T_ - s)) >> 1) <= idx) s++;
    const int e = s + (idx - ((s * (2 * T_ - s + 1)) >> 1));

    const float mf = (msk[b * T_ + s] != 0 && msk[b * T_ + e] != 0) ? 1.f : 0.f;
    out[b * K_ + t] = mf / (1.f + expf(-l));

    float pred = 0.f;
#pragma unroll
    for (int g = 0; g < NG_; g++)
        if (gold[g] == idx) pred = 1.f;

    const float bce = fmaxf(l, 0.f) - l * pred + log1pf(expf(-fabsf(l)));
    red[t] = mf * bce;
    __syncthreads();
#pragma unroll
    for (int off = 256; off > 0; off >>= 1) {
        if (t < off) red[t] += red[t + off];
        __syncthreads();
    }
    if (t == 0) g_loss[b] = red[0];
}

/* Kernel 4b: deterministic loss sum + pad zeroing. */
__global__ __launch_bounds__(256) void loss_sum_kernel(float* __restrict__ out, int out_size)
{
    const int t = threadIdx.x;
    for (int i = B_ * K_ + t; i < out_size - 1; i += 256) out[i] = 0.f;
    if (t == 0) {
        float s = 0.f;
#pragma unroll
        for (int b = 0; b < B_; b++) s += g_loss[b];
        out[out_size - 1] = s;
    }
}

/* ======================================================================= */
extern "C" void kernel_launch(void* const* d_in, const int* in_sizes, int n_in,
                              void* d_out, int out_size)
{
    const float* X   = (const float*)d_in[0];
    const int*   msk = (const int*)  d_in[1];
    const int*   asp = (const int*)  d_in[2];
    const float* Ws  = (const float*)d_in[3];
    const float* bs  = (const float*)d_in[4];
    const float* We  = (const float*)d_in[5];
    const float* be  = (const float*)d_in[6];
    const float* wsc = (const float*)d_in[7];
    const float* bsc = (const float*)d_in[8];
    float* out = (float*)d_out;

    static int smem_set = 0;
    if (!smem_set) {
        cudaFuncSetAttribute(gemm_mma,
                             cudaFuncAttributeMaxDynamicSharedMemorySize,
                             2 * STGF * (int)sizeof(float));
        smem_set = 1;
    }

    prep_A<<<(M_ * D_ / 4 + 255) / 256, 256>>>(X);
    prep_B<<<dim3(N_ / 32, D_ / 32), 256>>>(Ws, We);
    gemm_mma<<<dim3(8, 16), 256, 2 * STGF * sizeof(float)>>>(bs, be);
    score_kernel<<<dim3(36, 8), 256>>>(wsc, bsc, msk);
    topk_kernel<<<8, 1024>>>();
    finalize_kernel<<<8, 512>>>(msk, asp, out);
    loss_sum_kernel<<<1, 256>>>(out, out_size);
}

// round 5
// speedup vs baseline: 1.4206x; 1.1053x over previous
#include <cuda_runtime.h>
#include <stdint.h>
#include <math.h>

#define B_  8
#define T_  256
#define D_  1024
#define H_  512
#define S_  32896     /* T*(T+1)/2 */
#define K_  512
#define NG_ 10
#define NEGV (-1e20f)

#define M_  (B_ * T_)        /* 2048 */
#define N_  (2 * H_)         /* 1024: [start | end] */

/* ---------------- scratch (no allocations allowed) ---------------- */
__device__ float g_hs[B_ * T_ * H_];
__device__ float g_he[B_ * T_ * H_];
__device__ float g_scores[B_ * S_];
__device__ int   g_topidx[B_ * K_];
__device__ float g_loss[B_];

/* ======================= helpers ======================= */
__device__ __forceinline__ uint32_t f2tf32(float x)
{
    uint32_t r;
    asm("cvt.rna.tf32.f32 %0, %1;" : "=r"(r) : "f"(x));
    return r;
}

__device__ __forceinline__ void hilo(float x, uint32_t& hi, uint32_t& lo)
{
    hi = f2tf32(x);
    lo = f2tf32(x - __uint_as_float(hi));
}

__device__ __forceinline__ void cpasync16(uint32_t smem_dst, const void* gsrc)
{
    asm volatile("cp.async.cg.shared.global [%0], [%1], 16;"
                 :: "r"(smem_dst), "l"(gsrc));
}

__device__ __forceinline__ void mma_tf32(float* c, const uint32_t a[4], const uint32_t b[2])
{
    asm volatile(
        "mma.sync.aligned.m16n8k8.row.col.f32.tf32.tf32.f32 "
        "{%0,%1,%2,%3}, {%4,%5,%6,%7}, {%8,%9}, {%0,%1,%2,%3};"
        : "+f"(c[0]), "+f"(c[1]), "+f"(c[2]), "+f"(c[3])
        : "r"(a[0]), "r"(a[1]), "r"(a[2]), "r"(a[3]), "r"(b[0]), "r"(b[1]));
}

/* =======================================================================
 * Kernel 1: fused 3xTF32 tensor-core GEMM, fp32 inputs converted in-kernel.
 * C[2048 x 1024] = X @ [W_start | W_end] + bias.
 * CTA tile 128x128, BK=16, 2-stage cp.async pipeline, 256 threads.
 * A raw tile [m][k] 128x16 (pad 20); B raw tile [k][n] 16x128 (pad 136,
 * read transposed at fragment load; 136%32==8 -> conflict-free quads).
 * hi/lo tf32 split done in registers at fragment-load time.
 * ======================================================================= */
#define BK    16
#define LDPA  20
#define LDNB  136
#define AFLT  (128 * LDPA)          /* 2560 */
#define BFLT  (BK * LDNB)           /* 2176 */
#define STG   (AFLT + BFLT)         /* 4736 floats per stage */

__global__ __launch_bounds__(256) void gemm_fused(
    const float* __restrict__ X,
    const float* __restrict__ Ws, const float* __restrict__ bs,
    const float* __restrict__ We, const float* __restrict__ be)
{
    extern __shared__ float smem[];

    const int t  = threadIdx.x;
    const int bx = blockIdx.x;          /* 0..7  N tile */
    const int by = blockIdx.y;          /* 0..15 M tile */
    const int m0 = by * 128;

    const bool   isStart = (bx < 4);
    const float* W       = isStart ? Ws : We;
    const int    nc0     = (bx & 3) * 128;   /* column base within W */

    const int wid  = t >> 5;
    const int lane = t & 31;
    const int wm   = wid & 3;           /* M dir: 32 rows  */
    const int wn   = wid >> 2;          /* N dir: 64 cols  */
    const int gid  = lane >> 2;
    const int tig  = lane & 3;

    float acc[2][8][4];
#pragma unroll
    for (int mf = 0; mf < 2; mf++)
#pragma unroll
        for (int nf = 0; nf < 8; nf++)
#pragma unroll
            for (int r = 0; r < 4; r++) acc[mf][nf][r] = 0.f;

    /* ---- issue raw loads for a chunk into stage s ---- */
    auto issue = [&](int kc, int s) {
        const int k0 = kc * BK;
        float* stgA = smem + s * STG;
        float* stgB = stgA + AFLT;
        /* A: 128 rows x 16 cols = 512 float4 */
#pragma unroll
        for (int i = 0; i < 2; i++) {
            int id  = t + 256 * i;
            int row = id >> 2;
            int c4  = (id & 3) * 4;
            cpasync16((uint32_t)__cvta_generic_to_shared(stgA + row * LDPA + c4),
                      X + (size_t)(m0 + row) * D_ + k0 + c4);
        }
        /* B: 16 k-rows x 128 n-cols = 512 float4 */
#pragma unroll
        for (int i = 0; i < 2; i++) {
            int id   = t + 256 * i;
            int krow = id >> 5;
            int c4   = (id & 31) * 4;
            cpasync16((uint32_t)__cvta_generic_to_shared(stgB + krow * LDNB + c4),
                      W + (size_t)(k0 + krow) * H_ + nc0 + c4);
        }
        asm volatile("cp.async.commit_group;");
    };

    issue(0, 0);

    const int NCHUNK = D_ / BK;   /* 64 */
    for (int kc = 0; kc < NCHUNK; kc++) {
        const int cur = kc & 1;
        if (kc + 1 < NCHUNK) {
            issue(kc + 1, cur ^ 1);
            asm volatile("cp.async.wait_group 1;");
        } else {
            asm volatile("cp.async.wait_group 0;");
        }
        __syncthreads();

        const float* sA = smem + cur * STG;
        const float* sB = sA + AFLT;

#pragma unroll
        for (int ks = 0; ks < 2; ks++) {
            const int kb = ks * 8;
            uint32_t ah[2][4], al[2][4];
#pragma unroll
            for (int mf = 0; mf < 2; mf++) {
                int r = wm * 32 + mf * 16 + gid;
                int c = kb + tig;
                hilo(sA[r * LDPA + c],           ah[mf][0], al[mf][0]);
                hilo(sA[(r + 8) * LDPA + c],     ah[mf][1], al[mf][1]);
                hilo(sA[r * LDPA + c + 4],       ah[mf][2], al[mf][2]);
                hilo(sA[(r + 8) * LDPA + c + 4], ah[mf][3], al[mf][3]);
            }
            uint32_t bh[8][2], bl[8][2];
#pragma unroll
            for (int nf = 0; nf < 8; nf++) {
                int r = wn * 64 + nf * 8 + gid;   /* n index */
                int c = kb + tig;                  /* k index */
                hilo(sB[c * LDNB + r],       bh[nf][0], bl[nf][0]);
                hilo(sB[(c + 4) * LDNB + r], bh[nf][1], bl[nf][1]);
            }
#pragma unroll
            for (int mf = 0; mf < 2; mf++)
#pragma unroll
                for (int nf = 0; nf < 8; nf++) {
                    mma_tf32(acc[mf][nf], ah[mf], bh[nf]);
                    mma_tf32(acc[mf][nf], ah[mf], bl[nf]);
                    mma_tf32(acc[mf][nf], al[mf], bh[nf]);
                }
        }
        __syncthreads();
    }

    /* ---- epilogue: bias + store to g_hs / g_he ---- */
    float*       out  = isStart ? g_hs : g_he;
    const float* bias = isStart ? bs : be;

#pragma unroll
    for (int mf = 0; mf < 2; mf++) {
        int row = m0 + wm * 32 + mf * 16 + gid;
#pragma unroll
        for (int nf = 0; nf < 8; nf++) {
            int nl = nc0 + wn * 64 + nf * 8 + tig * 2;
            float b0 = bias[nl], b1 = bias[nl + 1];
            float2 v0 = make_float2(acc[mf][nf][0] + b0, acc[mf][nf][1] + b1);
            float2 v1 = make_float2(acc[mf][nf][2] + b0, acc[mf][nf][3] + b1);
            *(float2*)&out[(size_t)row * H_ + nl]       = v0;
            *(float2*)&out[(size_t)(row + 8) * H_ + nl] = v1;
        }
    }
}

/* =======================================================================
 * Kernel 2: span scoring — 32x32 (s,e) tiles, 288 blocks (round-4 version).
 * ======================================================================= */
#define SCH 32
__global__ __launch_bounds__(256) void score_kernel(
    const float* __restrict__ wsc, const float* __restrict__ bsc,
    const int* __restrict__ msk)
{
    __shared__ float sA[SCH][34];
    __shared__ float sB[SCH][34];
    __shared__ float sW[SCH];
    __shared__ int   sMs[32];
    __shared__ int   sMe[32];

    const int t = threadIdx.x;
    const int b = blockIdx.y;

    int q = blockIdx.x, ti = 0;
    while (q >= (8 - ti)) { q -= (8 - ti); ti++; }
    const int tj = ti + q;
    const int s0 = ti * 32;
    const int e0 = tj * 32;

    if (t < 32)      sMs[t]      = msk[b * T_ + s0 + t];
    else if (t < 64) sMe[t - 32] = msk[b * T_ + e0 + (t - 32)];

    const int sx = t & 15;
    const int ey = t >> 4;
    const int s_l = t >> 3;
    const int h_l = (t & 7) * 4;

    float acc00 = 0.f, acc01 = 0.f, acc10 = 0.f, acc11 = 0.f;

    for (int h0 = 0; h0 < H_; h0 += SCH) {
        __syncthreads();
        {
            float4 a = *(const float4*)(g_hs + (size_t)(b * T_ + s0 + s_l) * H_ + h0 + h_l);
            sA[h_l + 0][s_l] = a.x; sA[h_l + 1][s_l] = a.y;
            sA[h_l + 2][s_l] = a.z; sA[h_l + 3][s_l] = a.w;
            float4 e = *(const float4*)(g_he + (size_t)(b * T_ + e0 + s_l) * H_ + h0 + h_l);
            sB[h_l + 0][s_l] = e.x; sB[h_l + 1][s_l] = e.y;
            sB[h_l + 2][s_l] = e.z; sB[h_l + 3][s_l] = e.w;
            if (t < SCH) sW[t] = wsc[h0 + t];
        }
        __syncthreads();

#pragma unroll
        for (int h = 0; h < SCH; h++) {
            float2 av = *(const float2*)&sA[h][sx * 2];
            float2 bv = *(const float2*)&sB[h][ey * 2];
            float wv = sW[h];
            acc00 = fmaf(fmaxf(av.x + bv.x, 0.f), wv, acc00);
            acc01 = fmaf(fmaxf(av.x + bv.y, 0.f), wv, acc01);
            acc10 = fmaf(fmaxf(av.y + bv.x, 0.f), wv, acc10);
            acc11 = fmaf(fmaxf(av.y + bv.y, 0.f), wv, acc11);
        }
    }

    const float bval = bsc[0];
    float accs[2][2] = {{acc00, acc01}, {acc10, acc11}};
#pragma unroll
    for (int i = 0; i < 2; i++) {
        int s = s0 + sx * 2 + i;
        int base = (s * (2 * T_ - s + 1)) >> 1;
        int ms = sMs[sx * 2 + i];
#pragma unroll
        for (int j = 0; j < 2; j++) {
            int e = e0 + ey * 2 + j;
            if (e >= s) {
                float v = (ms && sMe[ey * 2 + j]) ? (accs[i][j] + bval) : NEGV;
                g_scores[b * S_ + base + (e - s)] = v;
            }
        }
    }
}

/* =======================================================================
 * Kernel 3: exact top-K — plain smem-atomic histogram (round-3 style,
 * the match_any aggregation regressed) + shuffle-based block scan.
 * ======================================================================= */
__device__ __forceinline__ unsigned fkey(float f)
{
    unsigned u = __float_as_uint(f);
    return u ^ ((u & 0x80000000u) ? 0xFFFFFFFFu : 0x80000000u);
}

__device__ int blockExclScan1024(int v)
{
    __shared__ int ws[32];
    const int lane = threadIdx.x & 31;
    const int wid  = threadIdx.x >> 5;

    int incl = v;
#pragma unroll
    for (int o = 1; o < 32; o <<= 1) {
        int x = __shfl_up_sync(0xFFFFFFFFu, incl, o);
        if (lane >= o) incl += x;
    }
    if (lane == 31) ws[wid] = incl;
    __syncthreads();
    if (wid == 0) {
        int s = ws[lane];
#pragma unroll
        for (int o = 1; o < 32; o <<= 1) {
            int x = __shfl_up_sync(0xFFFFFFFFu, s, o);
            if (lane >= o) s += x;
        }
        ws[lane] = s;
    }
    __syncthreads();
    int base = (wid > 0) ? ws[wid - 1] : 0;
    int r = base + incl - v;
    __syncthreads();
    return r;
}

__global__ __launch_bounds__(1024) void topk_kernel()
{
    const int b = blockIdx.x;
    const int t = threadIdx.x;
    const float* sc = g_scores + (size_t)b * S_;

    __shared__ unsigned hist[256];
    __shared__ unsigned sh_prefix;
    __shared__ int      sh_rem;

    unsigned prefix = 0;
    int rem = K_;

    for (int pass = 0; pass < 4; pass++) {
        const int shift = 24 - pass * 8;
        if (t < 256) hist[t] = 0;
        __syncthreads();
        for (int i = t; i < S_; i += 1024) {
            unsigned u = fkey(sc[i]);
            bool match = (pass == 0) ||
                         ((u >> (shift + 8)) == (prefix >> (shift + 8)));
            if (match) atomicAdd(&hist[(u >> shift) & 255u], 1u);
        }
        __syncthreads();
        if (t == 0) {
            int r = rem;
            int d = 255;
            for (; d > 0; d--) {
                int c = (int)hist[d];
                if (r - c <= 0) break;
                r -= c;
            }
            sh_prefix = prefix | ((unsigned)d << shift);
            sh_rem = r;
        }
        __syncthreads();
        prefix = sh_prefix;
        rem    = sh_rem;
        __syncthreads();
    }

    const unsigned thr = prefix;
    const int need_eq  = rem;

    const int CHK = (S_ + 1023) / 1024;   /* 33 */
    const int lo = t * CHK;
    const int hi = (lo + CHK < S_) ? (lo + CHK) : S_;

    int ceq = 0, cgt = 0;
    for (int i = lo; i < hi; i++) {
        unsigned u = fkey(sc[i]);
        if (u > thr) cgt++;
        else if (u == thr) ceq++;
    }

    int eq_excl = blockExclScan1024(ceq);
    int take_eq = need_eq - eq_excl;
    if (take_eq < 0) take_eq = 0;
    if (take_eq > ceq) take_eq = ceq;
    int inc = cgt + take_eq;
    int out_excl = blockExclScan1024(inc);

    int pos = out_excl;
    int eqrank = eq_excl;
    for (int i = lo; i < hi; i++) {
        unsigned u = fkey(sc[i]);
        if (u > thr) {
            g_topidx[b * K_ + pos++] = i;
        } else if (u == thr) {
            if (eqrank < need_eq) g_topidx[b * K_ + pos++] = i;
            eqrank++;
        }
    }
}

/* =======================================================================
 * Kernel 4a: per-batch gather + sigmoid + BCE partial sums (8 blocks).
 * ======================================================================= */
__global__ __launch_bounds__(512) void finalize_kernel(
    const int* __restrict__ msk, const int* __restrict__ spans,
    float* __restrict__ out)
{
    __shared__ int   gold[NG_];
    __shared__ float red[512];
    const int b = blockIdx.x;
    const int t = threadIdx.x;

    if (t < NG_) {
        int s = spans[(b * NG_ + t) * 2];
        int e = spans[(b * NG_ + t) * 2 + 1];
        int gi = -1;
        if (s >= 0) gi = ((2 * s * T_ - s * s + s) >> 1) + (e - s);
        gold[t] = gi;
    }
    __syncthreads();

    const int idx = g_topidx[b * K_ + t];
    const float l = g_scores[(size_t)b * S_ + idx];

    double disc = (double)(2 * T_ + 1) * (2 * T_ + 1) - 8.0 * (double)idx;
    int s = (int)(((2.0 * T_ + 1.0) - sqrt(disc)) * 0.5);
    if (s < 0) s = 0;
    if (s >= T_) s = T_ - 1;
    while (s > 0 && ((s * (2 * T_ - s + 1)) >> 1) > idx) s--;
    while (s + 1 < T_ && (((s + 1) * (2 * T_ - s)) >> 1) <= idx) s++;
    const int e = s + (idx - ((s * (2 * T_ - s + 1)) >> 1));

    const float mf = (msk[b * T_ + s] != 0 && msk[b * T_ + e] != 0) ? 1.f : 0.f;
    out[b * K_ + t] = mf / (1.f + expf(-l));

    float pred = 0.f;
#pragma unroll
    for (int g = 0; g < NG_; g++)
        if (gold[g] == idx) pred = 1.f;

    const float bce = fmaxf(l, 0.f) - l * pred + log1pf(expf(-fabsf(l)));
    red[t] = mf * bce;
    __syncthreads();
#pragma unroll
    for (int off = 256; off > 0; off >>= 1) {
        if (t < off) red[t] += red[t + off];
        __syncthreads();
    }
    if (t == 0) g_loss[b] = red[0];
}

/* Kernel 4b: deterministic loss sum + pad zeroing. */
__global__ __launch_bounds__(256) void loss_sum_kernel(float* __restrict__ out, int out_size)
{
    const int t = threadIdx.x;
    for (int i = B_ * K_ + t; i < out_size - 1; i += 256) out[i] = 0.f;
    if (t == 0) {
        float s = 0.f;
#pragma unroll
        for (int b = 0; b < B_; b++) s += g_loss[b];
        out[out_size - 1] = s;
    }
}

/* ======================================================================= */
extern "C" void kernel_launch(void* const* d_in, const int* in_sizes, int n_in,
                              void* d_out, int out_size)
{
    const float* X   = (const float*)d_in[0];
    const int*   msk = (const int*)  d_in[1];
    const int*   asp = (const int*)  d_in[2];
    const float* Ws  = (const float*)d_in[3];
    const float* bs  = (const float*)d_in[4];
    const float* We  = (const float*)d_in[5];
    const float* be  = (const float*)d_in[6];
    const float* wsc = (const float*)d_in[7];
    const float* bsc = (const float*)d_in[8];
    float* out = (float*)d_out;

    gemm_fused<<<dim3(8, 16), 256, 2 * STG * sizeof(float)>>>(X, Ws, bs, We, be);
    score_kernel<<<dim3(36, 8), 256>>>(wsc, bsc, msk);
    topk_kernel<<<8, 1024>>>();
    finalize_kernel<<<8, 512>>>(msk, asp, out);
    loss_sum_kernel<<<1, 256>>>(out, out_size);
}

// round 6
// speedup vs baseline: 1.6554x; 1.1652x over previous
#include <cuda_runtime.h>
#include <stdint.h>
#include <math.h>

#define B_  8
#define T_  256
#define D_  1024
#define H_  512
#define S_  32896     /* T*(T+1)/2 */
#define K_  512
#define NG_ 10
#define NEGV (-1e20f)

#define M_  (B_ * T_)        /* 2048 */
#define N_  (2 * H_)         /* 1024: [start | end] */

/* ---------------- scratch (no allocations allowed) ---------------- */
__device__ float g_hs[B_ * T_ * H_];
__device__ float g_he[B_ * T_ * H_];
__device__ float g_scores[B_ * S_];
__device__ int   g_topidx[B_ * K_];
__device__ float g_loss[B_];

/* ======================= helpers ======================= */
__device__ __forceinline__ uint32_t f2tf32(float x)
{
    uint32_t r;
    asm("cvt.rna.tf32.f32 %0, %1;" : "=r"(r) : "f"(x));
    return r;
}

__device__ __forceinline__ void hilo(float x, uint32_t& hi, uint32_t& lo)
{
    hi = f2tf32(x);
    lo = f2tf32(x - __uint_as_float(hi));
}

__device__ __forceinline__ void cpasync16(uint32_t smem_dst, const void* gsrc)
{
    asm volatile("cp.async.cg.shared.global [%0], [%1], 16;"
                 :: "r"(smem_dst), "l"(gsrc));
}

__device__ __forceinline__ void mma_tf32(float* c, const uint32_t a[4], const uint32_t b[2])
{
    asm volatile(
        "mma.sync.aligned.m16n8k8.row.col.f32.tf32.tf32.f32 "
        "{%0,%1,%2,%3}, {%4,%5,%6,%7}, {%8,%9}, {%0,%1,%2,%3};"
        : "+f"(c[0]), "+f"(c[1]), "+f"(c[2]), "+f"(c[3])
        : "r"(a[0]), "r"(a[1]), "r"(a[2]), "r"(a[3]), "r"(b[0]), "r"(b[1]));
}

/* =======================================================================
 * Kernel 1: fused 3xTF32 tensor-core GEMM (unchanged from round 5).
 * ======================================================================= */
#define BK    16
#define LDPA  20
#define LDNB  136
#define AFLT  (128 * LDPA)
#define BFLT  (BK * LDNB)
#define STG   (AFLT + BFLT)

__global__ __launch_bounds__(256) void gemm_fused(
    const float* __restrict__ X,
    const float* __restrict__ Ws, const float* __restrict__ bs,
    const float* __restrict__ We, const float* __restrict__ be)
{
    extern __shared__ float smem[];

    const int t  = threadIdx.x;
    const int bx = blockIdx.x;
    const int by = blockIdx.y;
    const int m0 = by * 128;

    const bool   isStart = (bx < 4);
    const float* W       = isStart ? Ws : We;
    const int    nc0     = (bx & 3) * 128;

    const int wid  = t >> 5;
    const int lane = t & 31;
    const int wm   = wid & 3;
    const int wn   = wid >> 2;
    const int gid  = lane >> 2;
    const int tig  = lane & 3;

    float acc[2][8][4];
#pragma unroll
    for (int mf = 0; mf < 2; mf++)
#pragma unroll
        for (int nf = 0; nf < 8; nf++)
#pragma unroll
            for (int r = 0; r < 4; r++) acc[mf][nf][r] = 0.f;

    auto issue = [&](int kc, int s) {
        const int k0 = kc * BK;
        float* stgA = smem + s * STG;
        float* stgB = stgA + AFLT;
#pragma unroll
        for (int i = 0; i < 2; i++) {
            int id  = t + 256 * i;
            int row = id >> 2;
            int c4  = (id & 3) * 4;
            cpasync16((uint32_t)__cvta_generic_to_shared(stgA + row * LDPA + c4),
                      X + (size_t)(m0 + row) * D_ + k0 + c4);
        }
#pragma unroll
        for (int i = 0; i < 2; i++) {
            int id   = t + 256 * i;
            int krow = id >> 5;
            int c4   = (id & 31) * 4;
            cpasync16((uint32_t)__cvta_generic_to_shared(stgB + krow * LDNB + c4),
                      W + (size_t)(k0 + krow) * H_ + nc0 + c4);
        }
        asm volatile("cp.async.commit_group;");
    };

    issue(0, 0);

    const int NCHUNK = D_ / BK;
    for (int kc = 0; kc < NCHUNK; kc++) {
        const int cur = kc & 1;
        if (kc + 1 < NCHUNK) {
            issue(kc + 1, cur ^ 1);
            asm volatile("cp.async.wait_group 1;");
        } else {
            asm volatile("cp.async.wait_group 0;");
        }
        __syncthreads();

        const float* sA = smem + cur * STG;
        const float* sB = sA + AFLT;

#pragma unroll
        for (int ks = 0; ks < 2; ks++) {
            const int kb = ks * 8;
            uint32_t ah[2][4], al[2][4];
#pragma unroll
            for (int mf = 0; mf < 2; mf++) {
                int r = wm * 32 + mf * 16 + gid;
                int c = kb + tig;
                hilo(sA[r * LDPA + c],           ah[mf][0], al[mf][0]);
                hilo(sA[(r + 8) * LDPA + c],     ah[mf][1], al[mf][1]);
                hilo(sA[r * LDPA + c + 4],       ah[mf][2], al[mf][2]);
                hilo(sA[(r + 8) * LDPA + c + 4], ah[mf][3], al[mf][3]);
            }
            uint32_t bh[8][2], bl[8][2];
#pragma unroll
            for (int nf = 0; nf < 8; nf++) {
                int r = wn * 64 + nf * 8 + gid;
                int c = kb + tig;
                hilo(sB[c * LDNB + r],       bh[nf][0], bl[nf][0]);
                hilo(sB[(c + 4) * LDNB + r], bh[nf][1], bl[nf][1]);
            }
#pragma unroll
            for (int mf = 0; mf < 2; mf++)
#pragma unroll
                for (int nf = 0; nf < 8; nf++) {
                    mma_tf32(acc[mf][nf], ah[mf], bh[nf]);
                    mma_tf32(acc[mf][nf], ah[mf], bl[nf]);
                    mma_tf32(acc[mf][nf], al[mf], bh[nf]);
                }
        }
        __syncthreads();
    }

    float*       out  = isStart ? g_hs : g_he;
    const float* bias = isStart ? bs : be;

#pragma unroll
    for (int mf = 0; mf < 2; mf++) {
        int row = m0 + wm * 32 + mf * 16 + gid;
#pragma unroll
        for (int nf = 0; nf < 8; nf++) {
            int nl = nc0 + wn * 64 + nf * 8 + tig * 2;
            float b0 = bias[nl], b1 = bias[nl + 1];
            float2 v0 = make_float2(acc[mf][nf][0] + b0, acc[mf][nf][1] + b1);
            float2 v1 = make_float2(acc[mf][nf][2] + b0, acc[mf][nf][3] + b1);
            *(float2*)&out[(size_t)row * H_ + nl]       = v0;
            *(float2*)&out[(size_t)(row + 8) * H_ + nl] = v1;
        }
    }
}

/* =======================================================================
 * Kernel 2: span scoring (unchanged from round 5).
 * ======================================================================= */
#define SCH 32
__global__ __launch_bounds__(256) void score_kernel(
    const float* __restrict__ wsc, const float* __restrict__ bsc,
    const int* __restrict__ msk)
{
    __shared__ float sA[SCH][34];
    __shared__ float sB[SCH][34];
    __shared__ float sW[SCH];
    __shared__ int   sMs[32];
    __shared__ int   sMe[32];

    const int t = threadIdx.x;
    const int b = blockIdx.y;

    int q = blockIdx.x, ti = 0;
    while (q >= (8 - ti)) { q -= (8 - ti); ti++; }
    const int tj = ti + q;
    const int s0 = ti * 32;
    const int e0 = tj * 32;

    if (t < 32)      sMs[t]      = msk[b * T_ + s0 + t];
    else if (t < 64) sMe[t - 32] = msk[b * T_ + e0 + (t - 32)];

    const int sx = t & 15;
    const int ey = t >> 4;
    const int s_l = t >> 3;
    const int h_l = (t & 7) * 4;

    float acc00 = 0.f, acc01 = 0.f, acc10 = 0.f, acc11 = 0.f;

    for (int h0 = 0; h0 < H_; h0 += SCH) {
        __syncthreads();
        {
            float4 a = *(const float4*)(g_hs + (size_t)(b * T_ + s0 + s_l) * H_ + h0 + h_l);
            sA[h_l + 0][s_l] = a.x; sA[h_l + 1][s_l] = a.y;
            sA[h_l + 2][s_l] = a.z; sA[h_l + 3][s_l] = a.w;
            float4 e = *(const float4*)(g_he + (size_t)(b * T_ + e0 + s_l) * H_ + h0 + h_l);
            sB[h_l + 0][s_l] = e.x; sB[h_l + 1][s_l] = e.y;
            sB[h_l + 2][s_l] = e.z; sB[h_l + 3][s_l] = e.w;
            if (t < SCH) sW[t] = wsc[h0 + t];
        }
        __syncthreads();

#pragma unroll
        for (int h = 0; h < SCH; h++) {
            float2 av = *(const float2*)&sA[h][sx * 2];
            float2 bv = *(const float2*)&sB[h][ey * 2];
            float wv = sW[h];
            acc00 = fmaf(fmaxf(av.x + bv.x, 0.f), wv, acc00);
            acc01 = fmaf(fmaxf(av.x + bv.y, 0.f), wv, acc01);
            acc10 = fmaf(fmaxf(av.y + bv.x, 0.f), wv, acc10);
            acc11 = fmaf(fmaxf(av.y + bv.y, 0.f), wv, acc11);
        }
    }

    const float bval = bsc[0];
    float accs[2][2] = {{acc00, acc01}, {acc10, acc11}};
#pragma unroll
    for (int i = 0; i < 2; i++) {
        int s = s0 + sx * 2 + i;
        int base = (s * (2 * T_ - s + 1)) >> 1;
        int ms = sMs[sx * 2 + i];
#pragma unroll
        for (int j = 0; j < 2; j++) {
            int e = e0 + ey * 2 + j;
            if (e >= s) {
                float v = (ms && sMe[ey * 2 + j]) ? (accs[i][j] + bval) : NEGV;
                g_scores[b * S_ + base + (e - s)] = v;
            }
        }
    }
}

/* =======================================================================
 * Kernel 3: exact top-K v3.
 * - all 32896 keys cached in dynamic smem (one global read)
 * - radix 12/12/8 (3 passes), spreads the exponent hot-bin 16x
 * - parallel suffix-scan digit selection (was serial 256-iter loop)
 * - ordered compaction from smem keys
 * ======================================================================= */
__device__ __forceinline__ unsigned fkey(float f)
{
    unsigned u = __float_as_uint(f);
    return u ^ ((u & 0x80000000u) ? 0xFFFFFFFFu : 0x80000000u);
}

/* exclusive scan over 1024 threads (shuffle + 32-entry smem) */
__device__ int blockExclScan1024(int v)
{
    __shared__ int ws[32];
    const int lane = threadIdx.x & 31;
    const int wid  = threadIdx.x >> 5;

    int incl = v;
#pragma unroll
    for (int o = 1; o < 32; o <<= 1) {
        int x = __shfl_up_sync(0xFFFFFFFFu, incl, o);
        if (lane >= o) incl += x;
    }
    if (lane == 31) ws[wid] = incl;
    __syncthreads();
    if (wid == 0) {
        int s = ws[lane];
#pragma unroll
        for (int o = 1; o < 32; o <<= 1) {
            int x = __shfl_up_sync(0xFFFFFFFFu, s, o);
            if (lane >= o) s += x;
        }
        ws[lane] = s;
    }
    __syncthreads();
    int base = (wid > 0) ? ws[wid - 1] : 0;
    int r = base + incl - v;
    __syncthreads();
    return r;
}

#define TK_BINS   4096
#define TOPK_SMEM ((S_ + TK_BINS) * 4)

__global__ __launch_bounds__(1024) void topk_kernel()
{
    extern __shared__ unsigned tks[];
    unsigned* keys = tks;          /* S_ entries  */
    unsigned* hist = tks + S_;     /* 4096 entries */

    __shared__ unsigned sh_prefix;
    __shared__ int      sh_rem;
    __shared__ int      sh_total;

    const int b = blockIdx.x;
    const int t = threadIdx.x;
    const float* sc = g_scores + (size_t)b * S_;

    /* phase 0: load + convert keys into smem (S_ = 8224 float4 exactly) */
    for (int i4 = t; i4 < S_ / 4; i4 += 1024) {
        float4 v = ((const float4*)sc)[i4];
        keys[i4 * 4 + 0] = fkey(v.x);
        keys[i4 * 4 + 1] = fkey(v.y);
        keys[i4 * 4 + 2] = fkey(v.z);
        keys[i4 * 4 + 3] = fkey(v.w);
    }
    __syncthreads();

    unsigned prefix = 0;
    int rem = K_;

#pragma unroll
    for (int p = 0; p < 3; p++) {
        const int shift = (p == 0) ? 20 : (p == 1) ? 8 : 0;
        const int bins  = (p == 2) ? 256 : TK_BINS;
        const int hb    = (p == 1) ? 20 : 8;   /* matching boundary (p>=1) */

        for (int i = t; i < bins; i += 1024) hist[i] = 0;
        __syncthreads();

        for (int i = t; i < S_; i += 1024) {
            unsigned u = keys[i];
            bool match = (p == 0) || ((u >> hb) == (prefix >> hb));
            if (match) atomicAdd(&hist[(u >> shift) & (unsigned)(bins - 1)], 1u);
        }
        __syncthreads();

        /* parallel selection: find largest digit d with suffix_sum(d) >= rem */
        const int BPT = (bins + 1023) >> 10;          /* 4 or 1 */
        int lo = t * BPT;
        int hi = lo + BPT;
        if (lo > bins) lo = bins;
        if (hi > bins) hi = bins;

        int s = 0;
        for (int j = lo; j < hi; j++) s += (int)hist[j];

        int excl = blockExclScan1024(s);              /* sum over threads < t */
        if (t == 1023) sh_total = excl + s;
        __syncthreads();
        int suff_above = sh_total - excl - s;         /* sum over threads > t */

        int c = suff_above;
        for (int j = hi - 1; j >= lo; j--) {
            int h = (int)hist[j];
            int ssum = c + h;
            if (ssum >= rem && c < rem) {             /* unique crossing */
                sh_prefix = prefix | ((unsigned)j << shift);
                sh_rem = rem - c;
            }
            c = ssum;
        }
        __syncthreads();
        prefix = sh_prefix;
        rem    = sh_rem;
        __syncthreads();
    }

    const unsigned thr = prefix;   /* exact key of the K-th largest */
    const int need_eq  = rem;      /* # of ==thr to take (ascending index) */

    const int CHK = (S_ + 1023) / 1024;   /* 33 */
    const int lo = t * CHK;
    const int hi = (lo + CHK < S_) ? (lo + CHK) : S_;

    int ceq = 0, cgt = 0;
    for (int i = lo; i < hi; i++) {
        unsigned u = keys[i];
        if (u > thr) cgt++;
        else if (u == thr) ceq++;
    }

    int eq_excl = blockExclScan1024(ceq);
    int take_eq = need_eq - eq_excl;
    if (take_eq < 0) take_eq = 0;
    if (take_eq > ceq) take_eq = ceq;
    int inc = cgt + take_eq;
    int out_excl = blockExclScan1024(inc);

    int pos = out_excl;
    int eqrank = eq_excl;
    for (int i = lo; i < hi; i++) {
        unsigned u = keys[i];
        if (u > thr) {
            g_topidx[b * K_ + pos++] = i;
        } else if (u == thr) {
            if (eqrank < need_eq) g_topidx[b * K_ + pos++] = i;
            eqrank++;
        }
    }
}

/* =======================================================================
 * Kernel 4a: per-batch gather + sigmoid + BCE partial sums (8 blocks).
 * fp32 triangular decode (all quantities exact in fp32; fixups handle
 * sqrt rounding).
 * ======================================================================= */
__global__ __launch_bounds__(512) void finalize_kernel(
    const int* __restrict__ msk, const int* __restrict__ spans,
    float* __restrict__ out)
{
    __shared__ int   gold[NG_];
    __shared__ float red[512];
    const int b = blockIdx.x;
    const int t = threadIdx.x;

    if (t < NG_) {
        int s = spans[(b * NG_ + t) * 2];
        int e = spans[(b * NG_ + t) * 2 + 1];
        int gi = -1;
        if (s >= 0) gi = ((2 * s * T_ - s * s + s) >> 1) + (e - s);
        gold[t] = gi;
    }
    __syncthreads();

    const int idx = g_topidx[b * K_ + t];
    const float l = g_scores[(size_t)b * S_ + idx];

    float disc = (float)((2 * T_ + 1) * (2 * T_ + 1) - 8 * idx);
    int s = (int)(((2.f * T_ + 1.f) - sqrtf(disc)) * 0.5f);
    if (s < 0) s = 0;
    if (s >= T_) s = T_ - 1;
    while (s > 0 && ((s * (2 * T_ - s + 1)) >> 1) > idx) s--;
    while (s + 1 < T_ && (((s + 1) * (2 * T_ - s)) >> 1) <= idx) s++;
    const int e = s + (idx - ((s * (2 * T_ - s + 1)) >> 1));

    const float mf = (msk[b * T_ + s] != 0 && msk[b * T_ + e] != 0) ? 1.f : 0.f;
    out[b * K_ + t] = mf / (1.f + expf(-l));

    float pred = 0.f;
#pragma unroll
    for (int g = 0; g < NG_; g++)
        if (gold[g] == idx) pred = 1.f;

    const float bce = fmaxf(l, 0.f) - l * pred + log1pf(expf(-fabsf(l)));
    red[t] = mf * bce;
    __syncthreads();
#pragma unroll
    for (int off = 256; off > 0; off >>= 1) {
        if (t < off) red[t] += red[t + off];
        __syncthreads();
    }
    if (t == 0) g_loss[b] = red[0];
}

/* Kernel 4b: deterministic loss sum + pad zeroing. */
__global__ __launch_bounds__(256) void loss_sum_kernel(float* __restrict__ out, int out_size)
{
    const int t = threadIdx.x;
    for (int i = B_ * K_ + t; i < out_size - 1; i += 256) out[i] = 0.f;
    if (t == 0) {
        float s = 0.f;
#pragma unroll
        for (int b = 0; b < B_; b++) s += g_loss[b];
        out[out_size - 1] = s;
    }
}

/* ======================================================================= */
extern "C" void kernel_launch(void* const* d_in, const int* in_sizes, int n_in,
                              void* d_out, int out_size)
{
    const float* X   = (const float*)d_in[0];
    const int*   msk = (const int*)  d_in[1];
    const int*   asp = (const int*)  d_in[2];
    const float* Ws  = (const float*)d_in[3];
    const float* bs  = (const float*)d_in[4];
    const float* We  = (const float*)d_in[5];
    const float* be  = (const float*)d_in[6];
    const float* wsc = (const float*)d_in[7];
    const float* bsc = (const float*)d_in[8];
    float* out = (float*)d_out;

    cudaFuncSetAttribute(topk_kernel,
                         cudaFuncAttributeMaxDynamicSharedMemorySize,
                         TOPK_SMEM);

    gemm_fused<<<dim3(8, 16), 256, 2 * STG * sizeof(float)>>>(X, Ws, bs, We, be);
    score_kernel<<<dim3(36, 8), 256>>>(wsc, bsc, msk);
    topk_kernel<<<8, 1024, TOPK_SMEM>>>();
    finalize_kernel<<<8, 512>>>(msk, asp, out);
    loss_sum_kernel<<<1, 256>>>(out, out_size);
}

// round 8
// speedup vs baseline: 1.7013x; 1.0277x over previous
#include <cuda_runtime.h>
#include <stdint.h>
#include <math.h>

#define B_  8
#define T_  256
#define D_  1024
#define H_  512
#define S_  32896     /* T*(T+1)/2 */
#define K_  512
#define NG_ 10
#define NEGV (-1e20f)

#define M_  (B_ * T_)        /* 2048 */
#define N_  (2 * H_)         /* 1024: [start | end] */

/* ---------------- scratch (no allocations allowed) ---------------- */
__device__ float g_hs[B_ * T_ * H_];
__device__ float g_he[B_ * T_ * H_];
__device__ float g_scores[B_ * S_];
__device__ int   g_topidx[B_ * K_];
__device__ float g_loss[B_];

/* bf16 split planes: A [m][k], B transposed [n][k]; packed bf16x2 words */
__device__ uint32_t g_A1[M_ * D_ / 2];
__device__ uint32_t g_A2[M_ * D_ / 2];
__device__ uint32_t g_A3[M_ * D_ / 2];
__device__ uint32_t g_B1[N_ * D_ / 2];
__device__ uint32_t g_B2[N_ * D_ / 2];
__device__ uint32_t g_B3[N_ * D_ / 2];

/* ======================= helpers ======================= */
__device__ __forceinline__ void cpasync16(uint32_t smem_dst, const void* gsrc)
{
    asm volatile("cp.async.cg.shared.global [%0], [%1], 16;"
                 :: "r"(smem_dst), "l"(gsrc));
}

/* exact 3-way bf16 truncation split: x == h1 + h2 + h3 bitwise (8+8+8 bits) */
__device__ __forceinline__ void split3(float x, uint32_t& h1, uint32_t& h2, uint32_t& h3)
{
    uint32_t u  = __float_as_uint(x);
    uint32_t u1 = u & 0xFFFF0000u;
    float    r1 = x - __uint_as_float(u1);
    uint32_t u2 = __float_as_uint(r1) & 0xFFFF0000u;
    float    r2 = r1 - __uint_as_float(u2);
    h1 = u1 >> 16;
    h2 = u2 >> 16;
    h3 = __float_as_uint(r2) >> 16;
}

__device__ __forceinline__ void mma_bf16(float* c, const uint32_t a[4], const uint32_t b[2])
{
    asm volatile(
        "mma.sync.aligned.m16n8k16.row.col.f32.bf16.bf16.f32 "
        "{%0,%1,%2,%3}, {%4,%5,%6,%7}, {%8,%9}, {%0,%1,%2,%3};"
        : "+f"(c[0]), "+f"(c[1]), "+f"(c[2]), "+f"(c[3])
        : "r"(a[0]), "r"(a[1]), "r"(a[2]), "r"(a[3]), "r"(b[0]), "r"(b[1]));
}

/* =======================================================================
 * prep_A_split: X -> 3 bf16 planes, same [m][k] layout.
 * ======================================================================= */
__global__ __launch_bounds__(256) void prep_A_split(const float* __restrict__ X)
{
    int i = (blockIdx.x * 256 + threadIdx.x) * 4;
    if (i >= M_ * D_) return;
    float4 v = *(const float4*)(X + i);
    uint32_t a1[4], a2[4], a3[4];
    split3(v.x, a1[0], a2[0], a3[0]);
    split3(v.y, a1[1], a2[1], a3[1]);
    split3(v.z, a1[2], a2[2], a3[2]);
    split3(v.w, a1[3], a2[3], a3[3]);
    uint2 p;
    int w = i >> 1;
    p.x = a1[0] | (a1[1] << 16); p.y = a1[2] | (a1[3] << 16);
    *(uint2*)&g_A1[w] = p;
    p.x = a2[0] | (a2[1] << 16); p.y = a2[2] | (a2[3] << 16);
    *(uint2*)&g_A2[w] = p;
    p.x = a3[0] | (a3[1] << 16); p.y = a3[2] | (a3[3] << 16);
    *(uint2*)&g_A3[w] = p;
}

/* =======================================================================
 * prep_B_split: [k][n] -> transposed [n][k], 3 bf16 planes. 32x32 tiles.
 * ======================================================================= */
__global__ __launch_bounds__(256) void prep_B_split(
    const float* __restrict__ Ws, const float* __restrict__ We)
{
    __shared__ float tile[32][33];
    const int t  = threadIdx.x;
    const int tx = t & 31;
    const int ty = t >> 5;
    const int n0 = blockIdx.x * 32;
    const int k0 = blockIdx.y * 32;

#pragma unroll
    for (int j = 0; j < 4; j++) {
        int k = k0 + ty + j * 8;
        int n = n0 + tx;
        tile[ty + j * 8][tx] = (n < H_) ? Ws[k * H_ + n] : We[k * H_ + (n - H_)];
    }
    __syncthreads();

#pragma unroll
    for (int j = 0; j < 2; j++) {
        int idx = t + 256 * j;        /* 0..511 */
        int nl  = idx >> 4;           /* 0..31  */
        int cw  = idx & 15;           /* word col: k pair 2cw */
        float x0 = tile[2 * cw][nl];
        float x1 = tile[2 * cw + 1][nl];
        uint32_t a1, a2, a3, b1, b2, b3;
        split3(x0, a1, a2, a3);
        split3(x1, b1, b2, b3);
        size_t w = ((size_t)(n0 + nl) * D_ + k0) / 2 + cw;
        g_B1[w] = a1 | (b1 << 16);
        g_B2[w] = a2 | (b2 << 16);
        g_B3[w] = a3 | (b3 << 16);
    }
}

/* =======================================================================
 * Kernel 1: bf16x6 tensor-core GEMM (exact fp32 split).
 * C[2048 x 1024] = X @ Wt^T + bias.
 * CTA tile 128x128, chunk K=32, 2-stage cp.async, 256 threads.
 * Smem plane: 128 rows x 80B (stride 20 words, conflict-free frag loads).
 * ======================================================================= */
#define CH      32
#define NCH     (D_ / CH)               /* 32 */
#define PLB     10240                   /* plane bytes: 128*80 */
#define PLW     2560                    /* plane words */
#define STGB    (6 * PLB)               /* 61440 B per stage */
#define GSMEM   (2 * STGB)              /* 122880 B */

__global__ __launch_bounds__(256) void gemm_bf16(
    const float* __restrict__ bs, const float* __restrict__ be)
{
    extern __shared__ uint32_t sw[];

    const int t  = threadIdx.x;
    const int bx = blockIdx.x;          /* 0..7  N tile */
    const int by = blockIdx.y;          /* 0..15 M tile */
    const int m0 = by * 128;
    const int nc0 = bx * 128;

    const int wid  = t >> 5;
    const int lane = t & 31;
    const int wm   = wid & 3;           /* M dir: 32 rows */
    const int wn   = wid >> 2;          /* N dir: 64 cols */
    const int gid  = lane >> 2;
    const int tig  = lane & 3;

    float acc[2][8][4];
#pragma unroll
    for (int mf = 0; mf < 2; mf++)
#pragma unroll
        for (int nf = 0; nf < 8; nf++)
#pragma unroll
            for (int r = 0; r < 4; r++) acc[mf][nf][r] = 0.f;

    /* 6 plane streams: bf16 rows of 2048 B (1024 halves) */
    const char* srcs[6];
    srcs[0] = (const char*)g_A1 + (size_t)m0 * 2048;
    srcs[1] = (const char*)g_A2 + (size_t)m0 * 2048;
    srcs[2] = (const char*)g_A3 + (size_t)m0 * 2048;
    srcs[3] = (const char*)g_B1 + (size_t)nc0 * 2048;
    srcs[4] = (const char*)g_B2 + (size_t)nc0 * 2048;
    srcs[5] = (const char*)g_B3 + (size_t)nc0 * 2048;

    auto issue = [&](int c, int s) {
        const int k0b = c * (CH * 2);   /* byte offset along k */
        char* stg = (char*)sw + s * STGB;
#pragma unroll
        for (int i = 0; i < 12; i++) {
            int idx = t + 256 * i;      /* 0..3071 */
            int pl  = idx >> 9;         /* 0..5 */
            int j   = idx & 511;
            int row = j >> 2;
            int c16 = j & 3;
            const char* src = srcs[pl] + (size_t)row * 2048 + k0b + c16 * 16;
            cpasync16((uint32_t)__cvta_generic_to_shared(
                          stg + pl * PLB + row * 80 + c16 * 16), src);
        }
        asm volatile("cp.async.commit_group;");
    };

    issue(0, 0);

    for (int c = 0; c < NCH; c++) {
        const int cur = c & 1;
        if (c + 1 < NCH) {
            issue(c + 1, cur ^ 1);
            asm volatile("cp.async.wait_group 1;");
        } else {
            asm volatile("cp.async.wait_group 0;");
        }
        __syncthreads();

        const uint32_t* Aw = sw + cur * (STGB / 4);
        const uint32_t* Bw = Aw + 3 * PLW;

#pragma unroll
        for (int ks = 0; ks < 2; ks++) {
            const int kw = ks * 8 + tig;
            uint32_t a[3][2][4];
#pragma unroll
            for (int p = 0; p < 3; p++)
#pragma unroll
                for (int mf = 0; mf < 2; mf++) {
                    int r = wm * 32 + mf * 16 + gid;
                    const uint32_t* pb = Aw + p * PLW + kw;
                    a[p][mf][0] = pb[r * 20];
                    a[p][mf][1] = pb[(r + 8) * 20];
                    a[p][mf][2] = pb[r * 20 + 4];
                    a[p][mf][3] = pb[(r + 8) * 20 + 4];
                }
#pragma unroll
            for (int nf = 0; nf < 8; nf++) {
                const int n = wn * 64 + nf * 8 + gid;
                uint32_t b[3][2];
#pragma unroll
                for (int p = 0; p < 3; p++) {
                    const uint32_t* pb = Bw + p * PLW + kw;
                    b[p][0] = pb[n * 20];
                    b[p][1] = pb[n * 20 + 4];
                }
#pragma unroll
                for (int mf = 0; mf < 2; mf++) {
                    mma_bf16(acc[mf][nf], a[0][mf], b[0]);
                    mma_bf16(acc[mf][nf], a[0][mf], b[1]);
                    mma_bf16(acc[mf][nf], a[1][mf], b[0]);
                    mma_bf16(acc[mf][nf], a[0][mf], b[2]);
                    mma_bf16(acc[mf][nf], a[1][mf], b[1]);
                    mma_bf16(acc[mf][nf], a[2][mf], b[0]);
                }
            }
        }
        __syncthreads();
    }

    /* ---- epilogue: bias + store ---- */
    const bool   isStart = (bx < 4);
    float*       out     = isStart ? g_hs : g_he;
    const float* bias    = isStart ? bs : be;
    const int    nbase   = (bx & 3) * 128;

#pragma unroll
    for (int mf = 0; mf < 2; mf++) {
        int row = m0 + wm * 32 + mf * 16 + gid;
#pragma unroll
        for (int nf = 0; nf < 8; nf++) {
            int nl = nbase + wn * 64 + nf * 8 + tig * 2;
            float b0 = bias[nl], b1 = bias[nl + 1];
            float2 v0 = make_float2(acc[mf][nf][0] + b0, acc[mf][nf][1] + b1);
            float2 v1 = make_float2(acc[mf][nf][2] + b0, acc[mf][nf][3] + b1);
            *(float2*)&out[(size_t)row * H_ + nl]       = v0;
            *(float2*)&out[(size_t)(row + 8) * H_ + nl] = v1;
        }
    }
}

/* =======================================================================
 * Kernel 2: span scoring (unchanged).
 * ======================================================================= */
#define SCH 32
__global__ __launch_bounds__(256) void score_kernel(
    const float* __restrict__ wsc, const float* __restrict__ bsc,
    const int* __restrict__ msk)
{
    __shared__ float sA[SCH][34];
    __shared__ float sB[SCH][34];
    __shared__ float sW[SCH];
    __shared__ int   sMs[32];
    __shared__ int   sMe[32];

    const int t = threadIdx.x;
    const int b = blockIdx.y;

    int q = blockIdx.x, ti = 0;
    while (q >= (8 - ti)) { q -= (8 - ti); ti++; }
    const int tj = ti + q;
    const int s0 = ti * 32;
    const int e0 = tj * 32;

    if (t < 32)      sMs[t]      = msk[b * T_ + s0 + t];
    else if (t < 64) sMe[t - 32] = msk[b * T_ + e0 + (t - 32)];

    const int sx = t & 15;
    const int ey = t >> 4;
    const int s_l = t >> 3;
    const int h_l = (t & 7) * 4;

    float acc00 = 0.f, acc01 = 0.f, acc10 = 0.f, acc11 = 0.f;

    for (int h0 = 0; h0 < H_; h0 += SCH) {
        __syncthreads();
        {
            float4 a = *(const float4*)(g_hs + (size_t)(b * T_ + s0 + s_l) * H_ + h0 + h_l);
            sA[h_l + 0][s_l] = a.x; sA[h_l + 1][s_l] = a.y;
            sA[h_l + 2][s_l] = a.z; sA[h_l + 3][s_l] = a.w;
            float4 e = *(const float4*)(g_he + (size_t)(b * T_ + e0 + s_l) * H_ + h0 + h_l);
            sB[h_l + 0][s_l] = e.x; sB[h_l + 1][s_l] = e.y;
            sB[h_l + 2][s_l] = e.z; sB[h_l + 3][s_l] = e.w;
            if (t < SCH) sW[t] = wsc[h0 + t];
        }
        __syncthreads();

#pragma unroll
        for (int h = 0; h < SCH; h++) {
            float2 av = *(const float2*)&sA[h][sx * 2];
            float2 bv = *(const float2*)&sB[h][ey * 2];
            float wv = sW[h];
            acc00 = fmaf(fmaxf(av.x + bv.x, 0.f), wv, acc00);
            acc01 = fmaf(fmaxf(av.x + bv.y, 0.f), wv, acc01);
            acc10 = fmaf(fmaxf(av.y + bv.x, 0.f), wv, acc10);
            acc11 = fmaf(fmaxf(av.y + bv.y, 0.f), wv, acc11);
        }
    }

    const float bval = bsc[0];
    float accs[2][2] = {{acc00, acc01}, {acc10, acc11}};
#pragma unroll
    for (int i = 0; i < 2; i++) {
        int s = s0 + sx * 2 + i;
        int base = (s * (2 * T_ - s + 1)) >> 1;
        int ms = sMs[sx * 2 + i];
#pragma unroll
        for (int j = 0; j < 2; j++) {
            int e = e0 + ey * 2 + j;
            if (e >= s) {
                float v = (ms && sMe[ey * 2 + j]) ? (accs[i][j] + bval) : NEGV;
                g_scores[b * S_ + base + (e - s)] = v;
            }
        }
    }
}

/* =======================================================================
 * Kernel 3: exact top-K (unchanged from round 6).
 * ======================================================================= */
__device__ __forceinline__ unsigned fkey(float f)
{
    unsigned u = __float_as_uint(f);
    return u ^ ((u & 0x80000000u) ? 0xFFFFFFFFu : 0x80000000u);
}

__device__ int blockExclScan1024(int v)
{
    __shared__ int ws[32];
    const int lane = threadIdx.x & 31;
    const int wid  = threadIdx.x >> 5;

    int incl = v;
#pragma unroll
    for (int o = 1; o < 32; o <<= 1) {
        int x = __shfl_up_sync(0xFFFFFFFFu, incl, o);
        if (lane >= o) incl += x;
    }
    if (lane == 31) ws[wid] = incl;
    __syncthreads();
    if (wid == 0) {
        int s = ws[lane];
#pragma unroll
        for (int o = 1; o < 32; o <<= 1) {
            int x = __shfl_up_sync(0xFFFFFFFFu, s, o);
            if (lane >= o) s += x;
        }
        ws[lane] = s;
    }
    __syncthreads();
    int base = (wid > 0) ? ws[wid - 1] : 0;
    int r = base + incl - v;
    __syncthreads();
    return r;
}

#define TK_BINS   4096
#define TOPK_SMEM ((S_ + TK_BINS) * 4)

__global__ __launch_bounds__(1024) void topk_kernel()
{
    extern __shared__ unsigned tks[];
    unsigned* keys = tks;
    unsigned* hist = tks + S_;

    __shared__ unsigned sh_prefix;
    __shared__ int      sh_rem;
    __shared__ int      sh_total;

    const int b = blockIdx.x;
    const int t = threadIdx.x;
    const float* sc = g_scores + (size_t)b * S_;

    for (int i4 = t; i4 < S_ / 4; i4 += 1024) {
        float4 v = ((const float4*)sc)[i4];
        keys[i4 * 4 + 0] = fkey(v.x);
        keys[i4 * 4 + 1] = fkey(v.y);
        keys[i4 * 4 + 2] = fkey(v.z);
        keys[i4 * 4 + 3] = fkey(v.w);
    }
    __syncthreads();

    unsigned prefix = 0;
    int rem = K_;

#pragma unroll
    for (int p = 0; p < 3; p++) {
        const int shift = (p == 0) ? 20 : (p == 1) ? 8 : 0;
        const int bins  = (p == 2) ? 256 : TK_BINS;
        const int hb    = (p == 1) ? 20 : 8;

        for (int i = t; i < bins; i += 1024) hist[i] = 0;
        __syncthreads();

        for (int i = t; i < S_; i += 1024) {
            unsigned u = keys[i];
            bool match = (p == 0) || ((u >> hb) == (prefix >> hb));
            if (match) atomicAdd(&hist[(u >> shift) & (unsigned)(bins - 1)], 1u);
        }
        __syncthreads();

        const int BPT = (bins + 1023) >> 10;
        int lo = t * BPT;
        int hi = lo + BPT;
        if (lo > bins) lo = bins;
        if (hi > bins) hi = bins;

        int s = 0;
        for (int j = lo; j < hi; j++) s += (int)hist[j];

        int excl = blockExclScan1024(s);
        if (t == 1023) sh_total = excl + s;
        __syncthreads();
        int suff_above = sh_total - excl - s;

        int c = suff_above;
        for (int j = hi - 1; j >= lo; j--) {
            int h = (int)hist[j];
            int ssum = c + h;
            if (ssum >= rem && c < rem) {
                sh_prefix = prefix | ((unsigned)j << shift);
                sh_rem = rem - c;
            }
            c = ssum;
        }
        __syncthreads();
        prefix = sh_prefix;
        rem    = sh_rem;
        __syncthreads();
    }

    const unsigned thr = prefix;
    const int need_eq  = rem;

    const int CHK = (S_ + 1023) / 1024;
    const int lo = t * CHK;
    const int hi = (lo + CHK < S_) ? (lo + CHK) : S_;

    int ceq = 0, cgt = 0;
    for (int i = lo; i < hi; i++) {
        unsigned u = keys[i];
        if (u > thr) cgt++;
        else if (u == thr) ceq++;
    }

    int eq_excl = blockExclScan1024(ceq);
    int take_eq = need_eq - eq_excl;
    if (take_eq < 0) take_eq = 0;
    if (take_eq > ceq) take_eq = ceq;
    int inc = cgt + take_eq;
    int out_excl = blockExclScan1024(inc);

    int pos = out_excl;
    int eqrank = eq_excl;
    for (int i = lo; i < hi; i++) {
        unsigned u = keys[i];
        if (u > thr) {
            g_topidx[b * K_ + pos++] = i;
        } else if (u == thr) {
            if (eqrank < need_eq) g_topidx[b * K_ + pos++] = i;
            eqrank++;
        }
    }
}

/* =======================================================================
 * Kernel 4a: per-batch gather + sigmoid + BCE partial sums.
 * ======================================================================= */
__global__ __launch_bounds__(512) void finalize_kernel(
    const int* __restrict__ msk, const int* __restrict__ spans,
    float* __restrict__ out)
{
    __shared__ int   gold[NG_];
    __shared__ float red[512];
    const int b = blockIdx.x;
    const int t = threadIdx.x;

    if (t < NG_) {
        int s = spans[(b * NG_ + t) * 2];
        int e = spans[(b * NG_ + t) * 2 + 1];
        int gi = -1;
        if (s >= 0) gi = ((2 * s * T_ - s * s + s) >> 1) + (e - s);
        gold[t] = gi;
    }
    __syncthreads();

    const int idx = g_topidx[b * K_ + t];
    const float l = g_scores[(size_t)b * S_ + idx];

    float disc = (float)((2 * T_ + 1) * (2 * T_ + 1) - 8 * idx);
    int s = (int)(((2.f * T_ + 1.f) - sqrtf(disc)) * 0.5f);
    if (s < 0) s = 0;
    if (s >= T_) s = T_ - 1;
    while (s > 0 && ((s * (2 * T_ - s + 1)) >> 1) > idx) s--;
    while (s + 1 < T_ && (((s + 1) * (2 * T_ - s)) >> 1) <= idx) s++;
    const int e = s + (idx - ((s * (2 * T_ - s + 1)) >> 1));

    const float mf = (msk[b * T_ + s] != 0 && msk[b * T_ + e] != 0) ? 1.f : 0.f;
    out[b * K_ + t] = mf / (1.f + expf(-l));

    float pred = 0.f;
#pragma unroll
    for (int g = 0; g < NG_; g++)
        if (gold[g] == idx) pred = 1.f;

    const float bce = fmaxf(l, 0.f) - l * pred + log1pf(expf(-fabsf(l)));
    red[t] = mf * bce;
    __syncthreads();
#pragma unroll
    for (int off = 256; off > 0; off >>= 1) {
        if (t < off) red[t] += red[t + off];
        __syncthreads();
    }
    if (t == 0) g_loss[b] = red[0];
}

__global__ __launch_bounds__(256) void loss_sum_kernel(float* __restrict__ out, int out_size)
{
    const int t = threadIdx.x;
    for (int i = B_ * K_ + t; i < out_size - 1; i += 256) out[i] = 0.f;
    if (t == 0) {
        float s = 0.f;
#pragma unroll
        for (int b = 0; b < B_; b++) s += g_loss[b];
        out[out_size - 1] = s;
    }
}

/* ======================================================================= */
extern "C" void kernel_launch(void* const* d_in, const int* in_sizes, int n_in,
                              void* d_out, int out_size)
{
    const float* X   = (const float*)d_in[0];
    const int*   msk = (const int*)  d_in[1];
    const int*   asp = (const int*)  d_in[2];
    const float* Ws  = (const float*)d_in[3];
    const float* bs  = (const float*)d_in[4];
    const float* We  = (const float*)d_in[5];
    const float* be  = (const float*)d_in[6];
    const float* wsc = (const float*)d_in[7];
    const float* bsc = (const float*)d_in[8];
    float* out = (float*)d_out;

    cudaFuncSetAttribute(gemm_bf16,
                         cudaFuncAttributeMaxDynamicSharedMemorySize, GSMEM);
    cudaFuncSetAttribute(topk_kernel,
                         cudaFuncAttributeMaxDynamicSharedMemorySize, TOPK_SMEM);

    prep_A_split<<<(M_ * D_ / 4 + 255) / 256, 256>>>(X);
    prep_B_split<<<dim3(N_ / 32, D_ / 32), 256>>>(Ws, We);
    gemm_bf16<<<dim3(8, 16), 256, GSMEM>>>(bs, be);
    score_kernel<<<dim3(36, 8), 256>>>(wsc, bsc, msk);
    topk_kernel<<<8, 1024, TOPK_SMEM>>>();
    finalize_kernel<<<8, 512>>>(msk, asp, out);
    loss_sum_kernel<<<1, 256>>>(out, out_size);
}

// round 9
// speedup vs baseline: 2.2794x; 1.3398x over previous
#include <cuda_runtime.h>
#include <cuda_fp16.h>
#include <stdint.h>
#include <math.h>

#define B_  8
#define T_  256
#define D_  1024
#define H_  512
#define S_  32896     /* T*(T+1)/2 */
#define K_  512
#define NG_ 10
#define NEGV (-1e20f)

#define M_  (B_ * T_)        /* 2048 */
#define N_  (2 * H_)         /* 1024: [start | end] */

/* ---------------- scratch (no allocations allowed) ---------------- */
__device__ float g_hs[B_ * T_ * H_];
__device__ float g_he[B_ * T_ * H_];
__device__ float g_scores[B_ * S_];
__device__ int   g_topidx[B_ * K_];
__device__ float g_loss[B_];

/* fp16 split planes: A [m][k], B transposed [n][k]; packed half2 words */
__device__ uint32_t g_A1[M_ * D_ / 2];
__device__ uint32_t g_A2[M_ * D_ / 2];
__device__ uint32_t g_B1[N_ * D_ / 2];
__device__ uint32_t g_B2[N_ * D_ / 2];

/* ======================= helpers ======================= */
__device__ __forceinline__ void cpasync16(uint32_t smem_dst, const void* gsrc)
{
    asm volatile("cp.async.cg.shared.global [%0], [%1], 16;"
                 :: "r"(smem_dst), "l"(gsrc));
}

/* 2-way fp16 split: x = h1 + h2 + O(2^-22 |x|) */
__device__ __forceinline__ void split2(float x, uint32_t& h1, uint32_t& h2)
{
    __half a = __float2half_rn(x);
    float  f = __half2float(a);
    __half b = __float2half_rn(x - f);
    h1 = (uint32_t)__half_as_ushort(a);
    h2 = (uint32_t)__half_as_ushort(b);
}

__device__ __forceinline__ void mma_f16(float* c, const uint32_t a[4], const uint32_t b[2])
{
    asm volatile(
        "mma.sync.aligned.m16n8k16.row.col.f32.f16.f16.f32 "
        "{%0,%1,%2,%3}, {%4,%5,%6,%7}, {%8,%9}, {%0,%1,%2,%3};"
        : "+f"(c[0]), "+f"(c[1]), "+f"(c[2]), "+f"(c[3])
        : "r"(a[0]), "r"(a[1]), "r"(a[2]), "r"(a[3]), "r"(b[0]), "r"(b[1]));
}

/* =======================================================================
 * prep_A_split: X -> 2 fp16 planes, same [m][k] layout.
 * ======================================================================= */
__global__ __launch_bounds__(256) void prep_A_split(const float* __restrict__ X)
{
    int i = (blockIdx.x * 256 + threadIdx.x) * 4;
    if (i >= M_ * D_) return;
    float4 v = *(const float4*)(X + i);
    uint32_t a1[4], a2[4];
    split2(v.x, a1[0], a2[0]);
    split2(v.y, a1[1], a2[1]);
    split2(v.z, a1[2], a2[2]);
    split2(v.w, a1[3], a2[3]);
    uint2 p;
    int w = i >> 1;
    p.x = a1[0] | (a1[1] << 16); p.y = a1[2] | (a1[3] << 16);
    *(uint2*)&g_A1[w] = p;
    p.x = a2[0] | (a2[1] << 16); p.y = a2[2] | (a2[3] << 16);
    *(uint2*)&g_A2[w] = p;
}

/* =======================================================================
 * prep_B_split: [k][n] -> transposed [n][k], 2 fp16 planes. 32x32 tiles.
 * ======================================================================= */
__global__ __launch_bounds__(256) void prep_B_split(
    const float* __restrict__ Ws, const float* __restrict__ We)
{
    __shared__ float tile[32][33];
    const int t  = threadIdx.x;
    const int tx = t & 31;
    const int ty = t >> 5;
    const int n0 = blockIdx.x * 32;
    const int k0 = blockIdx.y * 32;

#pragma unroll
    for (int j = 0; j < 4; j++) {
        int k = k0 + ty + j * 8;
        int n = n0 + tx;
        tile[ty + j * 8][tx] = (n < H_) ? Ws[k * H_ + n] : We[k * H_ + (n - H_)];
    }
    __syncthreads();

#pragma unroll
    for (int j = 0; j < 2; j++) {
        int idx = t + 256 * j;        /* 0..511 */
        int nl  = idx >> 4;           /* 0..31  */
        int cw  = idx & 15;           /* word col: k pair 2cw */
        float x0 = tile[2 * cw][nl];
        float x1 = tile[2 * cw + 1][nl];
        uint32_t a1, a2, b1, b2;
        split2(x0, a1, a2);
        split2(x1, b1, b2);
        size_t w = ((size_t)(n0 + nl) * D_ + k0) / 2 + cw;
        g_B1[w] = a1 | (b1 << 16);
        g_B2[w] = a2 | (b2 << 16);
    }
}

/* =======================================================================
 * Kernel 1: fp16x3 tensor-core GEMM (2-way fp16 split, 3 products).
 * C[2048 x 1024] = X @ Wt^T + bias.
 * CTA tile 128x128, chunk K=32, 2-stage cp.async, 256 threads.
 * Smem plane: 128 rows x 80B (stride 20 words, conflict-free frag loads).
 * ======================================================================= */
#define CH      32
#define NCH     (D_ / CH)               /* 32 */
#define PLB     10240                   /* plane bytes: 128*80 */
#define PLW     2560                    /* plane words */
#define STGB    (4 * PLB)               /* 40960 B per stage */
#define GSMEM   (2 * STGB)              /* 81920 B */

__global__ __launch_bounds__(256) void gemm_f16(
    const float* __restrict__ bs, const float* __restrict__ be)
{
    extern __shared__ uint32_t sw[];

    const int t  = threadIdx.x;
    const int bx = blockIdx.x;          /* 0..7  N tile */
    const int by = blockIdx.y;          /* 0..15 M tile */
    const int m0 = by * 128;
    const int nc0 = bx * 128;

    const int wid  = t >> 5;
    const int lane = t & 31;
    const int wm   = wid & 3;           /* M dir: 32 rows */
    const int wn   = wid >> 2;          /* N dir: 64 cols */
    const int gid  = lane >> 2;
    const int tig  = lane & 3;

    float acc[2][8][4];
#pragma unroll
    for (int mf = 0; mf < 2; mf++)
#pragma unroll
        for (int nf = 0; nf < 8; nf++)
#pragma unroll
            for (int r = 0; r < 4; r++) acc[mf][nf][r] = 0.f;

    /* 4 plane streams: fp16 rows of 2048 B */
    const char* srcs[4];
    srcs[0] = (const char*)g_A1 + (size_t)m0 * 2048;
    srcs[1] = (const char*)g_A2 + (size_t)m0 * 2048;
    srcs[2] = (const char*)g_B1 + (size_t)nc0 * 2048;
    srcs[3] = (const char*)g_B2 + (size_t)nc0 * 2048;

    auto issue = [&](int c, int s) {
        const int k0b = c * (CH * 2);   /* byte offset along k */
        char* stg = (char*)sw + s * STGB;
#pragma unroll
        for (int i = 0; i < 8; i++) {
            int idx = t + 256 * i;      /* 0..2047 */
            int pl  = idx >> 9;         /* 0..3 */
            int j   = idx & 511;
            int row = j >> 2;
            int c16 = j & 3;
            const char* src = srcs[pl] + (size_t)row * 2048 + k0b + c16 * 16;
            cpasync16((uint32_t)__cvta_generic_to_shared(
                          stg + pl * PLB + row * 80 + c16 * 16), src);
        }
        asm volatile("cp.async.commit_group;");
    };

    issue(0, 0);

    for (int c = 0; c < NCH; c++) {
        const int cur = c & 1;
        if (c + 1 < NCH) {
            issue(c + 1, cur ^ 1);
            asm volatile("cp.async.wait_group 1;");
        } else {
            asm volatile("cp.async.wait_group 0;");
        }
        __syncthreads();

        const uint32_t* Aw = sw + cur * (STGB / 4);
        const uint32_t* Bw = Aw + 2 * PLW;

#pragma unroll
        for (int ks = 0; ks < 2; ks++) {
            const int kw = ks * 8 + tig;
            uint32_t a[2][2][4];
#pragma unroll
            for (int p = 0; p < 2; p++)
#pragma unroll
                for (int mf = 0; mf < 2; mf++) {
                    int r = wm * 32 + mf * 16 + gid;
                    const uint32_t* pb = Aw + p * PLW + kw;
                    a[p][mf][0] = pb[r * 20];
                    a[p][mf][1] = pb[(r + 8) * 20];
                    a[p][mf][2] = pb[r * 20 + 4];
                    a[p][mf][3] = pb[(r + 8) * 20 + 4];
                }
#pragma unroll
            for (int nf = 0; nf < 8; nf++) {
                const int n = wn * 64 + nf * 8 + gid;
                uint32_t b[2][2];
#pragma unroll
                for (int p = 0; p < 2; p++) {
                    const uint32_t* pb = Bw + p * PLW + kw;
                    b[p][0] = pb[n * 20];
                    b[p][1] = pb[n * 20 + 4];
                }
#pragma unroll
                for (int mf = 0; mf < 2; mf++) {
                    mma_f16(acc[mf][nf], a[0][mf], b[0]);
                    mma_f16(acc[mf][nf], a[0][mf], b[1]);
                    mma_f16(acc[mf][nf], a[1][mf], b[0]);
                }
            }
        }
        __syncthreads();
    }

    /* ---- epilogue: bias + store ---- */
    const bool   isStart = (bx < 4);
    float*       out     = isStart ? g_hs : g_he;
    const float* bias    = isStart ? bs : be;
    const int    nbase   = (bx & 3) * 128;

#pragma unroll
    for (int mf = 0; mf < 2; mf++) {
        int row = m0 + wm * 32 + mf * 16 + gid;
#pragma unroll
        for (int nf = 0; nf < 8; nf++) {
            int nl = nbase + wn * 64 + nf * 8 + tig * 2;
            float b0 = bias[nl], b1 = bias[nl + 1];
            float2 v0 = make_float2(acc[mf][nf][0] + b0, acc[mf][nf][1] + b1);
            float2 v1 = make_float2(acc[mf][nf][2] + b0, acc[mf][nf][3] + b1);
            *(float2*)&out[(size_t)row * H_ + nl]       = v0;
            *(float2*)&out[(size_t)(row + 8) * H_ + nl] = v1;
        }
    }
}

/* =======================================================================
 * Kernel 2: span scoring (unchanged).
 * ======================================================================= */
#define SCH 32
__global__ __launch_bounds__(256) void score_kernel(
    const float* __restrict__ wsc, const float* __restrict__ bsc,
    const int* __restrict__ msk)
{
    __shared__ float sA[SCH][34];
    __shared__ float sB[SCH][34];
    __shared__ float sW[SCH];
    __shared__ int   sMs[32];
    __shared__ int   sMe[32];

    const int t = threadIdx.x;
    const int b = blockIdx.y;

    int q = blockIdx.x, ti = 0;
    while (q >= (8 - ti)) { q -= (8 - ti); ti++; }
    const int tj = ti + q;
    const int s0 = ti * 32;
    const int e0 = tj * 32;

    if (t < 32)      sMs[t]      = msk[b * T_ + s0 + t];
    else if (t < 64) sMe[t - 32] = msk[b * T_ + e0 + (t - 32)];

    const int sx = t & 15;
    const int ey = t >> 4;
    const int s_l = t >> 3;
    const int h_l = (t & 7) * 4;

    float acc00 = 0.f, acc01 = 0.f, acc10 = 0.f, acc11 = 0.f;

    for (int h0 = 0; h0 < H_; h0 += SCH) {
        __syncthreads();
        {
            float4 a = *(const float4*)(g_hs + (size_t)(b * T_ + s0 + s_l) * H_ + h0 + h_l);
            sA[h_l + 0][s_l] = a.x; sA[h_l + 1][s_l] = a.y;
            sA[h_l + 2][s_l] = a.z; sA[h_l + 3][s_l] = a.w;
            float4 e = *(const float4*)(g_he + (size_t)(b * T_ + e0 + s_l) * H_ + h0 + h_l);
            sB[h_l + 0][s_l] = e.x; sB[h_l + 1][s_l] = e.y;
            sB[h_l + 2][s_l] = e.z; sB[h_l + 3][s_l] = e.w;
            if (t < SCH) sW[t] = wsc[h0 + t];
        }
        __syncthreads();

#pragma unroll
        for (int h = 0; h < SCH; h++) {
            float2 av = *(const float2*)&sA[h][sx * 2];
            float2 bv = *(const float2*)&sB[h][ey * 2];
            float wv = sW[h];
            acc00 = fmaf(fmaxf(av.x + bv.x, 0.f), wv, acc00);
            acc01 = fmaf(fmaxf(av.x + bv.y, 0.f), wv, acc01);
            acc10 = fmaf(fmaxf(av.y + bv.x, 0.f), wv, acc10);
            acc11 = fmaf(fmaxf(av.y + bv.y, 0.f), wv, acc11);
        }
    }

    const float bval = bsc[0];
    float accs[2][2] = {{acc00, acc01}, {acc10, acc11}};
#pragma unroll
    for (int i = 0; i < 2; i++) {
        int s = s0 + sx * 2 + i;
        int base = (s * (2 * T_ - s + 1)) >> 1;
        int ms = sMs[sx * 2 + i];
#pragma unroll
        for (int j = 0; j < 2; j++) {
            int e = e0 + ey * 2 + j;
            if (e >= s) {
                float v = (ms && sMe[ey * 2 + j]) ? (accs[i][j] + bval) : NEGV;
                g_scores[b * S_ + base + (e - s)] = v;
            }
        }
    }
}

/* =======================================================================
 * Kernel 3: exact top-K (unchanged from round 6).
 * ======================================================================= */
__device__ __forceinline__ unsigned fkey(float f)
{
    unsigned u = __float_as_uint(f);
    return u ^ ((u & 0x80000000u) ? 0xFFFFFFFFu : 0x80000000u);
}

__device__ int blockExclScan1024(int v)
{
    __shared__ int ws[32];
    const int lane = threadIdx.x & 31;
    const int wid  = threadIdx.x >> 5;

    int incl = v;
#pragma unroll
    for (int o = 1; o < 32; o <<= 1) {
        int x = __shfl_up_sync(0xFFFFFFFFu, incl, o);
        if (lane >= o) incl += x;
    }
    if (lane == 31) ws[wid] = incl;
    __syncthreads();
    if (wid == 0) {
        int s = ws[lane];
#pragma unroll
        for (int o = 1; o < 32; o <<= 1) {
            int x = __shfl_up_sync(0xFFFFFFFFu, s, o);
            if (lane >= o) s += x;
        }
        ws[lane] = s;
    }
    __syncthreads();
    int base = (wid > 0) ? ws[wid - 1] : 0;
    int r = base + incl - v;
    __syncthreads();
    return r;
}

#define TK_BINS   4096
#define TOPK_SMEM ((S_ + TK_BINS) * 4)

__global__ __launch_bounds__(1024) void topk_kernel()
{
    extern __shared__ unsigned tks[];
    unsigned* keys = tks;
    unsigned* hist = tks + S_;

    __shared__ unsigned sh_prefix;
    __shared__ int      sh_rem;
    __shared__ int      sh_total;

    const int b = blockIdx.x;
    const int t = threadIdx.x;
    const float* sc = g_scores + (size_t)b * S_;

    for (int i4 = t; i4 < S_ / 4; i4 += 1024) {
        float4 v = ((const float4*)sc)[i4];
        keys[i4 * 4 + 0] = fkey(v.x);
        keys[i4 * 4 + 1] = fkey(v.y);
        keys[i4 * 4 + 2] = fkey(v.z);
        keys[i4 * 4 + 3] = fkey(v.w);
    }
    __syncthreads();

    unsigned prefix = 0;
    int rem = K_;

#pragma unroll
    for (int p = 0; p < 3; p++) {
        const int shift = (p == 0) ? 20 : (p == 1) ? 8 : 0;
        const int bins  = (p == 2) ? 256 : TK_BINS;
        const int hb    = (p == 1) ? 20 : 8;

        for (int i = t; i < bins; i += 1024) hist[i] = 0;
        __syncthreads();

        for (int i = t; i < S_; i += 1024) {
            unsigned u = keys[i];
            bool match = (p == 0) || ((u >> hb) == (prefix >> hb));
            if (match) atomicAdd(&hist[(u >> shift) & (unsigned)(bins - 1)], 1u);
        }
        __syncthreads();

        const int BPT = (bins + 1023) >> 10;
        int lo = t * BPT;
        int hi = lo + BPT;
        if (lo > bins) lo = bins;
        if (hi > bins) hi = bins;

        int s = 0;
        for (int j = lo; j < hi; j++) s += (int)hist[j];

        int excl = blockExclScan1024(s);
        if (t == 1023) sh_total = excl + s;
        __syncthreads();
        int suff_above = sh_total - excl - s;

        int c = suff_above;
        for (int j = hi - 1; j >= lo; j--) {
            int h = (int)hist[j];
            int ssum = c + h;
            if (ssum >= rem && c < rem) {
                sh_prefix = prefix | ((unsigned)j << shift);
                sh_rem = rem - c;
            }
            c = ssum;
        }
        __syncthreads();
        prefix = sh_prefix;
        rem    = sh_rem;
        __syncthreads();
    }

    const unsigned thr = prefix;
    const int need_eq  = rem;

    const int CHK = (S_ + 1023) / 1024;
    const int lo = t * CHK;
    const int hi = (lo + CHK < S_) ? (lo + CHK) : S_;

    int ceq = 0, cgt = 0;
    for (int i = lo; i < hi; i++) {
        unsigned u = keys[i];
        if (u > thr) cgt++;
        else if (u == thr) ceq++;
    }

    int eq_excl = blockExclScan1024(ceq);
    int take_eq = need_eq - eq_excl;
    if (take_eq < 0) take_eq = 0;
    if (take_eq > ceq) take_eq = ceq;
    int inc = cgt + take_eq;
    int out_excl = blockExclScan1024(inc);

    int pos = out_excl;
    int eqrank = eq_excl;
    for (int i = lo; i < hi; i++) {
        unsigned u = keys[i];
        if (u > thr) {
            g_topidx[b * K_ + pos++] = i;
        } else if (u == thr) {
            if (eqrank < need_eq) g_topidx[b * K_ + pos++] = i;
            eqrank++;
        }
    }
}

/* =======================================================================
 * Kernel 4a: per-batch gather + sigmoid + BCE partial sums.
 * ======================================================================= */
__global__ __launch_bounds__(512) void finalize_kernel(
    const int* __restrict__ msk, const int* __restrict__ spans,
    float* __restrict__ out)
{
    __shared__ int   gold[NG_];
    __shared__ float red[512];
    const int b = blockIdx.x;
    const int t = threadIdx.x;

    if (t < NG_) {
        int s = spans[(b * NG_ + t) * 2];
        int e = spans[(b * NG_ + t) * 2 + 1];
        int gi = -1;
        if (s >= 0) gi = ((2 * s * T_ - s * s + s) >> 1) + (e - s);
        gold[t] = gi;
    }
    __syncthreads();

    const int idx = g_topidx[b * K_ + t];
    const float l = g_scores[(size_t)b * S_ + idx];

    float disc = (float)((2 * T_ + 1) * (2 * T_ + 1) - 8 * idx);
    int s = (int)(((2.f * T_ + 1.f) - sqrtf(disc)) * 0.5f);
    if (s < 0) s = 0;
    if (s >= T_) s = T_ - 1;
    while (s > 0 && ((s * (2 * T_ - s + 1)) >> 1) > idx) s--;
    while (s + 1 < T_ && (((s + 1) * (2 * T_ - s)) >> 1) <= idx) s++;
    const int e = s + (idx - ((s * (2 * T_ - s + 1)) >> 1));

    const float mf = (msk[b * T_ + s] != 0 && msk[b * T_ + e] != 0) ? 1.f : 0.f;
    out[b * K_ + t] = mf / (1.f + expf(-l));

    float pred = 0.f;
#pragma unroll
    for (int g = 0; g < NG_; g++)
        if (gold[g] == idx) pred = 1.f;

    const float bce = fmaxf(l, 0.f) - l * pred + log1pf(expf(-fabsf(l)));
    red[t] = mf * bce;
    __syncthreads();
#pragma unroll
    for (int off = 256; off > 0; off >>= 1) {
        if (t < off) red[t] += red[t + off];
        __syncthreads();
    }
    if (t == 0) g_loss[b] = red[0];
}

__global__ __launch_bounds__(256) void loss_sum_kernel(float* __restrict__ out, int out_size)
{
    const int t = threadIdx.x;
    for (int i = B_ * K_ + t; i < out_size - 1; i += 256) out[i] = 0.f;
    if (t == 0) {
        float s = 0.f;
#pragma unroll
        for (int b = 0; b < B_; b++) s += g_loss[b];
        out[out_size - 1] = s;
    }
}

/* ======================================================================= */
extern "C" void kernel_launch(void* const* d_in, const int* in_sizes, int n_in,
                              void* d_out, int out_size)
{
    const float* X   = (const float*)d_in[0];
    const int*   msk = (const int*)  d_in[1];
    const int*   asp = (const int*)  d_in[2];
    const float* Ws  = (const float*)d_in[3];
    const float* bs  = (const float*)d_in[4];
    const float* We  = (const float*)d_in[5];
    const float* be  = (const float*)d_in[6];
    const float* wsc = (const float*)d_in[7];
    const float* bsc = (const float*)d_in[8];
    float* out = (float*)d_out;

    cudaFuncSetAttribute(gemm_f16,
                         cudaFuncAttributeMaxDynamicSharedMemorySize, GSMEM);
    cudaFuncSetAttribute(topk_kernel,
                         cudaFuncAttributeMaxDynamicSharedMemorySize, TOPK_SMEM);

    prep_A_split<<<(M_ * D_ / 4 + 255) / 256, 256>>>(X);
    prep_B_split<<<dim3(N_ / 32, D_ / 32), 256>>>(Ws, We);
    gemm_f16<<<dim3(8, 16), 256, GSMEM>>>(bs, be);
    score_kernel<<<dim3(36, 8), 256>>>(wsc, bsc, msk);
    topk_kernel<<<8, 1024, TOPK_SMEM>>>();
    finalize_kernel<<<8, 512>>>(msk, asp, out);
    loss_sum_kernel<<<1, 256>>>(out, out_size);
}

// round 10
// speedup vs baseline: 2.3232x; 1.0192x over previous
#include <cuda_runtime.h>
#include <cuda_fp16.h>
#include <stdint.h>
#include <math.h>

#define B_  8
#define T_  256
#define D_  1024
#define H_  512
#define S_  32896     /* T*(T+1)/2 */
#define K_  512
#define NG_ 10
#define NEGV (-1e20f)

#define M_  (B_ * T_)        /* 2048 */
#define N_  (2 * H_)         /* 1024: [start | end] */

/* ---------------- scratch (no allocations allowed) ---------------- */
__device__ float g_hs[B_ * T_ * H_];
__device__ float g_he[B_ * T_ * H_];
__device__ float g_scores[B_ * S_];
__device__ float g_part[2 * B_ * S_];   /* H-half partial span scores */
__device__ float g_loss[B_];

/* fp16 split planes: A [m][k], B transposed [n][k]; packed half2 words */
__device__ uint32_t g_A1[M_ * D_ / 2];
__device__ uint32_t g_A2[M_ * D_ / 2];
__device__ uint32_t g_B1[N_ * D_ / 2];
__device__ uint32_t g_B2[N_ * D_ / 2];

/* ======================= helpers ======================= */
__device__ __forceinline__ void cpasync16(uint32_t smem_dst, const void* gsrc)
{
    asm volatile("cp.async.cg.shared.global [%0], [%1], 16;"
                 :: "r"(smem_dst), "l"(gsrc));
}

/* 2-way fp16 split: x = h1 + h2 + O(2^-22 |x|) */
__device__ __forceinline__ void split2(float x, uint32_t& h1, uint32_t& h2)
{
    __half a = __float2half_rn(x);
    float  f = __half2float(a);
    __half b = __float2half_rn(x - f);
    h1 = (uint32_t)__half_as_ushort(a);
    h2 = (uint32_t)__half_as_ushort(b);
}

__device__ __forceinline__ void mma_f16(float* c, const uint32_t a[4], const uint32_t b[2])
{
    asm volatile(
        "mma.sync.aligned.m16n8k16.row.col.f32.f16.f16.f32 "
        "{%0,%1,%2,%3}, {%4,%5,%6,%7}, {%8,%9}, {%0,%1,%2,%3};"
        : "+f"(c[0]), "+f"(c[1]), "+f"(c[2]), "+f"(c[3])
        : "r"(a[0]), "r"(a[1]), "r"(a[2]), "r"(a[3]), "r"(b[0]), "r"(b[1]));
}

/* =======================================================================
 * prep_A_split: X -> 2 fp16 planes, same [m][k] layout.
 * ======================================================================= */
__global__ __launch_bounds__(256) void prep_A_split(const float* __restrict__ X)
{
    int i = (blockIdx.x * 256 + threadIdx.x) * 4;
    if (i >= M_ * D_) return;
    float4 v = *(const float4*)(X + i);
    uint32_t a1[4], a2[4];
    split2(v.x, a1[0], a2[0]);
    split2(v.y, a1[1], a2[1]);
    split2(v.z, a1[2], a2[2]);
    split2(v.w, a1[3], a2[3]);
    uint2 p;
    int w = i >> 1;
    p.x = a1[0] | (a1[1] << 16); p.y = a1[2] | (a1[3] << 16);
    *(uint2*)&g_A1[w] = p;
    p.x = a2[0] | (a2[1] << 16); p.y = a2[2] | (a2[3] << 16);
    *(uint2*)&g_A2[w] = p;
}

/* =======================================================================
 * prep_B_split: [k][n] -> transposed [n][k], 2 fp16 planes. 32x32 tiles.
 * ======================================================================= */
__global__ __launch_bounds__(256) void prep_B_split(
    const float* __restrict__ Ws, const float* __restrict__ We)
{
    __shared__ float tile[32][33];
    const int t  = threadIdx.x;
    const int tx = t & 31;
    const int ty = t >> 5;
    const int n0 = blockIdx.x * 32;
    const int k0 = blockIdx.y * 32;

#pragma unroll
    for (int j = 0; j < 4; j++) {
        int k = k0 + ty + j * 8;
        int n = n0 + tx;
        tile[ty + j * 8][tx] = (n < H_) ? Ws[k * H_ + n] : We[k * H_ + (n - H_)];
    }
    __syncthreads();

#pragma unroll
    for (int j = 0; j < 2; j++) {
        int idx = t + 256 * j;
        int nl  = idx >> 4;
        int cw  = idx & 15;
        float x0 = tile[2 * cw][nl];
        float x1 = tile[2 * cw + 1][nl];
        uint32_t a1, a2, b1, b2;
        split2(x0, a1, a2);
        split2(x1, b1, b2);
        size_t w = ((size_t)(n0 + nl) * D_ + k0) / 2 + cw;
        g_B1[w] = a1 | (b1 << 16);
        g_B2[w] = a2 | (b2 << 16);
    }
}

/* =======================================================================
 * Kernel 1: fp16x3 tensor-core GEMM (unchanged from round 9).
 * ======================================================================= */
#define CH      32
#define NCH     (D_ / CH)
#define PLB     10240
#define PLW     2560
#define STGB    (4 * PLB)
#define GSMEM   (2 * STGB)

__global__ __launch_bounds__(256) void gemm_f16(
    const float* __restrict__ bs, const float* __restrict__ be)
{
    extern __shared__ uint32_t sw[];

    const int t  = threadIdx.x;
    const int bx = blockIdx.x;
    const int by = blockIdx.y;
    const int m0 = by * 128;
    const int nc0 = bx * 128;

    const int wid  = t >> 5;
    const int lane = t & 31;
    const int wm   = wid & 3;
    const int wn   = wid >> 2;
    const int gid  = lane >> 2;
    const int tig  = lane & 3;

    float acc[2][8][4];
#pragma unroll
    for (int mf = 0; mf < 2; mf++)
#pragma unroll
        for (int nf = 0; nf < 8; nf++)
#pragma unroll
            for (int r = 0; r < 4; r++) acc[mf][nf][r] = 0.f;

    const char* srcs[4];
    srcs[0] = (const char*)g_A1 + (size_t)m0 * 2048;
    srcs[1] = (const char*)g_A2 + (size_t)m0 * 2048;
    srcs[2] = (const char*)g_B1 + (size_t)nc0 * 2048;
    srcs[3] = (const char*)g_B2 + (size_t)nc0 * 2048;

    auto issue = [&](int c, int s) {
        const int k0b = c * (CH * 2);
        char* stg = (char*)sw + s * STGB;
#pragma unroll
        for (int i = 0; i < 8; i++) {
            int idx = t + 256 * i;
            int pl  = idx >> 9;
            int j   = idx & 511;
            int row = j >> 2;
            int c16 = j & 3;
            const char* src = srcs[pl] + (size_t)row * 2048 + k0b + c16 * 16;
            cpasync16((uint32_t)__cvta_generic_to_shared(
                          stg + pl * PLB + row * 80 + c16 * 16), src);
        }
        asm volatile("cp.async.commit_group;");
    };

    issue(0, 0);

    for (int c = 0; c < NCH; c++) {
        const int cur = c & 1;
        if (c + 1 < NCH) {
            issue(c + 1, cur ^ 1);
            asm volatile("cp.async.wait_group 1;");
        } else {
            asm volatile("cp.async.wait_group 0;");
        }
        __syncthreads();

        const uint32_t* Aw = sw + cur * (STGB / 4);
        const uint32_t* Bw = Aw + 2 * PLW;

#pragma unroll
        for (int ks = 0; ks < 2; ks++) {
            const int kw = ks * 8 + tig;
            uint32_t a[2][2][4];
#pragma unroll
            for (int p = 0; p < 2; p++)
#pragma unroll
                for (int mf = 0; mf < 2; mf++) {
                    int r = wm * 32 + mf * 16 + gid;
                    const uint32_t* pb = Aw + p * PLW + kw;
                    a[p][mf][0] = pb[r * 20];
                    a[p][mf][1] = pb[(r + 8) * 20];
                    a[p][mf][2] = pb[r * 20 + 4];
                    a[p][mf][3] = pb[(r + 8) * 20 + 4];
                }
#pragma unroll
            for (int nf = 0; nf < 8; nf++) {
                const int n = wn * 64 + nf * 8 + gid;
                uint32_t b[2][2];
#pragma unroll
                for (int p = 0; p < 2; p++) {
                    const uint32_t* pb = Bw + p * PLW + kw;
                    b[p][0] = pb[n * 20];
                    b[p][1] = pb[n * 20 + 4];
                }
#pragma unroll
                for (int mf = 0; mf < 2; mf++) {
                    mma_f16(acc[mf][nf], a[0][mf], b[0]);
                    mma_f16(acc[mf][nf], a[0][mf], b[1]);
                    mma_f16(acc[mf][nf], a[1][mf], b[0]);
                }
            }
        }
        __syncthreads();
    }

    const bool   isStart = (bx < 4);
    float*       out     = isStart ? g_hs : g_he;
    const float* bias    = isStart ? bs : be;
    const int    nbase   = (bx & 3) * 128;

#pragma unroll
    for (int mf = 0; mf < 2; mf++) {
        int row = m0 + wm * 32 + mf * 16 + gid;
#pragma unroll
        for (int nf = 0; nf < 8; nf++) {
            int nl = nbase + wn * 64 + nf * 8 + tig * 2;
            float b0 = bias[nl], b1 = bias[nl + 1];
            float2 v0 = make_float2(acc[mf][nf][0] + b0, acc[mf][nf][1] + b1);
            float2 v1 = make_float2(acc[mf][nf][2] + b0, acc[mf][nf][3] + b1);
            *(float2*)&out[(size_t)row * H_ + nl]       = v0;
            *(float2*)&out[(size_t)(row + 8) * H_ + nl] = v1;
        }
    }
}

/* =======================================================================
 * Kernel 2a: span scoring halves — grid (36, 8, 2); z = H half.
 * Writes unbiased, unmasked partial sums to g_part[z][b][span].
 * ======================================================================= */
#define SCH 32
__global__ __launch_bounds__(256) void score_half(const float* __restrict__ wsc)
{
    __shared__ float sA[SCH][34];
    __shared__ float sB[SCH][34];
    __shared__ float sW[SCH];

    const int t = threadIdx.x;
    const int b = blockIdx.y;
    const int z = blockIdx.z;
    const int hoff = z * (H_ / 2);

    int q = blockIdx.x, ti = 0;
    while (q >= (8 - ti)) { q -= (8 - ti); ti++; }
    const int tj = ti + q;
    const int s0 = ti * 32;
    const int e0 = tj * 32;

    const int sx = t & 15;
    const int ey = t >> 4;
    const int s_l = t >> 3;
    const int h_l = (t & 7) * 4;

    float acc00 = 0.f, acc01 = 0.f, acc10 = 0.f, acc11 = 0.f;

    for (int h0 = 0; h0 < H_ / 2; h0 += SCH) {
        __syncthreads();
        {
            float4 a = *(const float4*)(g_hs + (size_t)(b * T_ + s0 + s_l) * H_ + hoff + h0 + h_l);
            sA[h_l + 0][s_l] = a.x; sA[h_l + 1][s_l] = a.y;
            sA[h_l + 2][s_l] = a.z; sA[h_l + 3][s_l] = a.w;
            float4 e = *(const float4*)(g_he + (size_t)(b * T_ + e0 + s_l) * H_ + hoff + h0 + h_l);
            sB[h_l + 0][s_l] = e.x; sB[h_l + 1][s_l] = e.y;
            sB[h_l + 2][s_l] = e.z; sB[h_l + 3][s_l] = e.w;
            if (t < SCH) sW[t] = wsc[hoff + h0 + t];
        }
        __syncthreads();

#pragma unroll
        for (int h = 0; h < SCH; h++) {
            float2 av = *(const float2*)&sA[h][sx * 2];
            float2 bv = *(const float2*)&sB[h][ey * 2];
            float wv = sW[h];
            acc00 = fmaf(fmaxf(av.x + bv.x, 0.f), wv, acc00);
            acc01 = fmaf(fmaxf(av.x + bv.y, 0.f), wv, acc01);
            acc10 = fmaf(fmaxf(av.y + bv.x, 0.f), wv, acc10);
            acc11 = fmaf(fmaxf(av.y + bv.y, 0.f), wv, acc11);
        }
    }

    float* part = g_part + (size_t)(z * B_ + b) * S_;
    float accs[2][2] = {{acc00, acc01}, {acc10, acc11}};
#pragma unroll
    for (int i = 0; i < 2; i++) {
        int s = s0 + sx * 2 + i;
        int base = (s * (2 * T_ - s + 1)) >> 1;
#pragma unroll
        for (int j = 0; j < 2; j++) {
            int e = e0 + ey * 2 + j;
            if (e >= s) part[base + (e - s)] = accs[i][j];
        }
    }
}

/* =======================================================================
 * Kernel 2b: combine halves + bias + mask -> g_scores. Grid (T_, B_).
 * ======================================================================= */
__global__ __launch_bounds__(128) void score_combine(
    const int* __restrict__ msk, const float* __restrict__ bsc)
{
    const int s = blockIdx.x;
    const int b = blockIdx.y;
    const int base = (s * (2 * T_ - s + 1)) >> 1;
    const int len = T_ - s;
    const int ms = msk[b * T_ + s];
    const float bias = bsc[0];

    const float* p0 = g_part + (size_t)b * S_ + base;
    const float* p1 = g_part + (size_t)(B_ + b) * S_ + base;
    float* dst = g_scores + (size_t)b * S_ + base;

    for (int o = threadIdx.x; o < len; o += 128) {
        float v = NEGV;
        if (ms && msk[b * T_ + s + o]) v = p0[o] + p1[o] + bias;
        dst[o] = v;
    }
}

/* =======================================================================
 * Kernel 3: exact top-K + fused finalize (gather/sigmoid/BCE).
 * ======================================================================= */
__device__ __forceinline__ unsigned fkey(float f)
{
    unsigned u = __float_as_uint(f);
    return u ^ ((u & 0x80000000u) ? 0xFFFFFFFFu : 0x80000000u);
}

__device__ __forceinline__ float unfkey(unsigned u)
{
    return (u & 0x80000000u) ? __uint_as_float(u ^ 0x80000000u)
                             : __uint_as_float(~u);
}

__device__ int blockExclScan1024(int v)
{
    __shared__ int ws[32];
    const int lane = threadIdx.x & 31;
    const int wid  = threadIdx.x >> 5;

    int incl = v;
#pragma unroll
    for (int o = 1; o < 32; o <<= 1) {
        int x = __shfl_up_sync(0xFFFFFFFFu, incl, o);
        if (lane >= o) incl += x;
    }
    if (lane == 31) ws[wid] = incl;
    __syncthreads();
    if (wid == 0) {
        int s = ws[lane];
#pragma unroll
        for (int o = 1; o < 32; o <<= 1) {
            int x = __shfl_up_sync(0xFFFFFFFFu, s, o);
            if (lane >= o) s += x;
        }
        ws[lane] = s;
    }
    __syncthreads();
    int base = (wid > 0) ? ws[wid - 1] : 0;
    int r = base + incl - v;
    __syncthreads();
    return r;
}

#define TK_BINS   4096
#define TOPK_SMEM ((S_ + TK_BINS) * 4)

__global__ __launch_bounds__(1024) void topk_kernel(
    const int* __restrict__ msk, const int* __restrict__ spans,
    float* __restrict__ out)
{
    extern __shared__ unsigned tks[];
    unsigned* keys = tks;
    unsigned* hist = tks + S_;

    __shared__ unsigned sh_prefix;
    __shared__ int      sh_rem;
    __shared__ int      sh_total;
    __shared__ int      gold[NG_];

    const int b = blockIdx.x;
    const int t = threadIdx.x;
    const float* sc = g_scores + (size_t)b * S_;

    if (t < NG_) {
        int s = spans[(b * NG_ + t) * 2];
        int e = spans[(b * NG_ + t) * 2 + 1];
        int gi = -1;
        if (s >= 0) gi = ((2 * s * T_ - s * s + s) >> 1) + (e - s);
        gold[t] = gi;
    }

    for (int i4 = t; i4 < S_ / 4; i4 += 1024) {
        float4 v = ((const float4*)sc)[i4];
        keys[i4 * 4 + 0] = fkey(v.x);
        keys[i4 * 4 + 1] = fkey(v.y);
        keys[i4 * 4 + 2] = fkey(v.z);
        keys[i4 * 4 + 3] = fkey(v.w);
    }
    __syncthreads();

    unsigned prefix = 0;
    int rem = K_;

#pragma unroll
    for (int p = 0; p < 3; p++) {
        const int shift = (p == 0) ? 20 : (p == 1) ? 8 : 0;
        const int bins  = (p == 2) ? 256 : TK_BINS;
        const int hb    = (p == 1) ? 20 : 8;

        for (int i = t; i < bins; i += 1024) hist[i] = 0;
        __syncthreads();

        for (int i = t; i < S_; i += 1024) {
            unsigned u = keys[i];
            bool match = (p == 0) || ((u >> hb) == (prefix >> hb));
            if (match) atomicAdd(&hist[(u >> shift) & (unsigned)(bins - 1)], 1u);
        }
        __syncthreads();

        const int BPT = (bins + 1023) >> 10;
        int lo = t * BPT;
        int hi = lo + BPT;
        if (lo > bins) lo = bins;
        if (hi > bins) hi = bins;

        int s = 0;
        for (int j = lo; j < hi; j++) s += (int)hist[j];

        int excl = blockExclScan1024(s);
        if (t == 1023) sh_total = excl + s;
        __syncthreads();
        int suff_above = sh_total - excl - s;

        int c = suff_above;
        for (int j = hi - 1; j >= lo; j--) {
            int h = (int)hist[j];
            int ssum = c + h;
            if (ssum >= rem && c < rem) {
                sh_prefix = prefix | ((unsigned)j << shift);
                sh_rem = rem - c;
            }
            c = ssum;
        }
        __syncthreads();
        prefix = sh_prefix;
        rem    = sh_rem;
        __syncthreads();
    }

    const unsigned thr = prefix;
    const int need_eq  = rem;

    const int CHK = (S_ + 1023) / 1024;
    const int lo = t * CHK;
    const int hi = (lo + CHK < S_) ? (lo + CHK) : S_;

    int ceq = 0, cgt = 0;
    for (int i = lo; i < hi; i++) {
        unsigned u = keys[i];
        if (u > thr) cgt++;
        else if (u == thr) ceq++;
    }

    int eq_excl = blockExclScan1024(ceq);
    int take_eq = need_eq - eq_excl;
    if (take_eq < 0) take_eq = 0;
    if (take_eq > ceq) take_eq = ceq;
    int inc = cgt + take_eq;
    int out_excl = blockExclScan1024(inc);

    int* sidx = (int*)hist;     /* hist region free after selection */
    int pos = out_excl;
    int eqrank = eq_excl;
    for (int i = lo; i < hi; i++) {
        unsigned u = keys[i];
        if (u > thr) {
            sidx[pos++] = i;
        } else if (u == thr) {
            if (eqrank < need_eq) sidx[pos++] = i;
            eqrank++;
        }
    }
    __syncthreads();

    /* ---- fused finalize: gather + sigmoid + BCE partial sum ---- */
    float contrib = 0.f;
    if (t < K_) {
        const int idx = sidx[t];
        const float l = unfkey(keys[idx]);

        float disc = (float)((2 * T_ + 1) * (2 * T_ + 1) - 8 * idx);
        int s = (int)(((2.f * T_ + 1.f) - sqrtf(disc)) * 0.5f);
        if (s < 0) s = 0;
        if (s >= T_) s = T_ - 1;
        while (s > 0 && ((s * (2 * T_ - s + 1)) >> 1) > idx) s--;
        while (s + 1 < T_ && (((s + 1) * (2 * T_ - s)) >> 1) <= idx) s++;
        const int e = s + (idx - ((s * (2 * T_ - s + 1)) >> 1));

        const float mf = (msk[b * T_ + s] != 0 && msk[b * T_ + e] != 0) ? 1.f : 0.f;
        out[b * K_ + t] = mf / (1.f + expf(-l));

        float pred = 0.f;
#pragma unroll
        for (int g = 0; g < NG_; g++)
            if (gold[g] == idx) pred = 1.f;

        contrib = mf * (fmaxf(l, 0.f) - l * pred + log1pf(expf(-fabsf(l))));
    }
    __syncthreads();                 /* keys reads done -> reuse as red[] */

    float* red = (float*)keys;
    red[t] = contrib;
    __syncthreads();
#pragma unroll
    for (int off = 512; off > 0; off >>= 1) {
        if (t < off) red[t] += red[t + off];
        __syncthreads();
    }
    if (t == 0) g_loss[b] = red[0];
}

/* Kernel 4: deterministic loss sum + pad zeroing. */
__global__ __launch_bounds__(256) void loss_sum_kernel(float* __restrict__ out, int out_size)
{
    const int t = threadIdx.x;
    for (int i = B_ * K_ + t; i < out_size - 1; i += 256) out[i] = 0.f;
    if (t == 0) {
        float s = 0.f;
#pragma unroll
        for (int b = 0; b < B_; b++) s += g_loss[b];
        out[out_size - 1] = s;
    }
}

/* ======================================================================= */
extern "C" void kernel_launch(void* const* d_in, const int* in_sizes, int n_in,
                              void* d_out, int out_size)
{
    const float* X   = (const float*)d_in[0];
    const int*   msk = (const int*)  d_in[1];
    const int*   asp = (const int*)  d_in[2];
    const float* Ws  = (const float*)d_in[3];
    const float* bs  = (const float*)d_in[4];
    const float* We  = (const float*)d_in[5];
    const float* be  = (const float*)d_in[6];
    const float* wsc = (const float*)d_in[7];
    const float* bsc = (const float*)d_in[8];
    float* out = (float*)d_out;

    cudaFuncSetAttribute(gemm_f16,
                         cudaFuncAttributeMaxDynamicSharedMemorySize, GSMEM);
    cudaFuncSetAttribute(topk_kernel,
                         cudaFuncAttributeMaxDynamicSharedMemorySize, TOPK_SMEM);

    prep_A_split<<<(M_ * D_ / 4 + 255) / 256, 256>>>(X);
    prep_B_split<<<dim3(N_ / 32, D_ / 32), 256>>>(Ws, We);
    gemm_f16<<<dim3(8, 16), 256, GSMEM>>>(bs, be);
    score_half<<<dim3(36, 8, 2), 256>>>(wsc);
    score_combine<<<dim3(T_, B_), 128>>>(msk, bsc);
    topk_kernel<<<8, 1024, TOPK_SMEM>>>(msk, asp, out);
    loss_sum_kernel<<<1, 256>>>(out, out_size);
}